// round 14
// baseline (speedup 1.0000x reference)
#include <cuda_runtime.h>
#include <cuda_bf16.h>
#include <cuda_fp16.h>

// ---------------- problem constants ----------------
#define NN 50000
#define EE 400000
#define DD 128
#define HH 60
#define H3 180
#define CC 40
#define BN_EPS 1e-5f

// ---------------- static scratch ----------------
__device__ __half g_Zr16[NN * 120];   // raw p=1,2 projections (fp16)
__device__ __half g_Zs16[NN * 64];    // raw hop-1 result for p=2 (fp16)
__device__ float g_Ha[NN * H3];
__device__ float g_Hb[NN * H3];
__device__ float g_scale[3 * H3];
__device__ float g_shift[3 * H3];
__device__ int   g_cnt[NN];           // zero-init; re-zeroed by scanwrite each call
__device__ int   g_ptr[NN + 1];
__device__ int   g_cursor[NN];
__device__ int   g_blockSum[256];
__device__ int   g_srcIdx[EE];
__device__ float g_enorm[EE];
__device__ float g_dis[NN];

// ---------------- CSR build ----------------
// 4 edges per thread via int4 (MLP=4 on DRAM-latency-bound edge reads)
__global__ void hist_kernel(const int* __restrict__ col, int* __restrict__ cnt, int E) {
    int e4 = (blockIdx.x * blockDim.x + threadIdx.x) * 4;
    if (e4 + 3 < E) {
        int4 c4 = *reinterpret_cast<const int4*>(col + e4);
        atomicAdd(&cnt[c4.x], 1);
        atomicAdd(&cnt[c4.y], 1);
        atomicAdd(&cnt[c4.z], 1);
        atomicAdd(&cnt[c4.w], 1);
    } else {
        for (int e = e4; e < E; e++) atomicAdd(&cnt[col[e]], 1);
    }
}

// per-256-block sums of cnt
__global__ void partial_kernel(const int* __restrict__ cnt, int* __restrict__ blockSum, int n) {
    __shared__ int ws[8];
    int i = blockIdx.x * 256 + threadIdx.x;
    int lane = threadIdx.x & 31, wid = threadIdx.x >> 5;
    int v = (i < n) ? cnt[i] : 0;
    #pragma unroll
    for (int off = 16; off > 0; off >>= 1) v += __shfl_down_sync(0xffffffffu, v, off);
    if (lane == 0) ws[wid] = v;
    __syncthreads();
    if (wid == 0) {
        int s = (lane < 8) ? ws[lane] : 0;
        #pragma unroll
        for (int off = 4; off > 0; off >>= 1) s += __shfl_down_sync(0xffffffffu, s, off);
        if (lane == 0) blockSum[blockIdx.x] = s;
    }
}

// fused: scan blockSum (redundantly per block), then per-chunk scan,
// write ptr/cursor/dis, and zero cnt for the next call/replay.
__global__ void scanwrite_kernel(int* __restrict__ cnt, const int* __restrict__ blockSum,
                                 int* __restrict__ ptr, int* __restrict__ cursor,
                                 float* __restrict__ dis, int n, int nBlocks) {
    __shared__ int ws[8];
    __shared__ int sOff[256];
    const int tid = threadIdx.x, lane = tid & 31, wid = tid >> 5;

    // phase A: exclusive scan of blockSum[0..nBlocks) into sOff
    int bv = (tid < nBlocks) ? blockSum[tid] : 0;
    int bx = bv;
    #pragma unroll
    for (int off = 1; off < 32; off <<= 1) {
        int t = __shfl_up_sync(0xffffffffu, bx, off);
        if (lane >= off) bx += t;
    }
    if (lane == 31) ws[wid] = bx;
    __syncthreads();
    if (wid == 0 && lane < 8) {
        int w = ws[lane];
        #pragma unroll
        for (int off = 1; off < 8; off <<= 1) {
            int t = __shfl_up_sync(0xffu, w, off);
            if (lane >= off) w += t;
        }
        ws[lane] = w;
    }
    __syncthreads();
    {
        int bwoff = wid ? ws[wid - 1] : 0;
        sOff[tid] = bwoff + bx - bv;
    }
    __syncthreads();
    const int myOff = sOff[blockIdx.x];
    __syncthreads();   // ws reused below

    // phase B: per-chunk scan
    int i = blockIdx.x * 256 + tid;
    int v = (i < n) ? cnt[i] : 0;
    int x = v;
    #pragma unroll
    for (int off = 1; off < 32; off <<= 1) {
        int t = __shfl_up_sync(0xffffffffu, x, off);
        if (lane >= off) x += t;
    }
    if (lane == 31) ws[wid] = x;
    __syncthreads();
    if (wid == 0 && lane < 8) {
        int w = ws[lane];
        #pragma unroll
        for (int off = 1; off < 8; off <<= 1) {
            int t = __shfl_up_sync(0xffu, w, off);
            if (lane >= off) w += t;
        }
        ws[lane] = w;
    }
    __syncthreads();
    int woff = wid ? ws[wid - 1] : 0;
    int excl = myOff + woff + x - v;
    if (i < n) {
        ptr[i] = excl;
        cursor[i] = excl;
        dis[i] = rsqrtf((float)(v + 1));   // +1 self loop
        if (i == n - 1) ptr[n] = excl + v;
        cnt[i] = 0;                         // reset for next call / replay
    }
}

// 4 edges per thread via int4
__global__ void scatter_kernel(const int* __restrict__ row, const int* __restrict__ col,
                               const float* __restrict__ dis, int* __restrict__ cursor,
                               int* __restrict__ srcIdx, float* __restrict__ enorm, int E) {
    int e4 = (blockIdx.x * blockDim.x + threadIdx.x) * 4;
    if (e4 + 3 < E) {
        int4 r4 = *reinterpret_cast<const int4*>(row + e4);
        int4 c4 = *reinterpret_cast<const int4*>(col + e4);
        float dr0 = dis[r4.x], dr1 = dis[r4.y], dr2 = dis[r4.z], dr3 = dis[r4.w];
        float dc0 = dis[c4.x], dc1 = dis[c4.y], dc2 = dis[c4.z], dc3 = dis[c4.w];
        int p0 = atomicAdd(&cursor[c4.x], 1);
        int p1 = atomicAdd(&cursor[c4.y], 1);
        int p2 = atomicAdd(&cursor[c4.z], 1);
        int p3 = atomicAdd(&cursor[c4.w], 1);
        srcIdx[p0] = r4.x; enorm[p0] = dr0 * dc0;
        srcIdx[p1] = r4.y; enorm[p1] = dr1 * dc1;
        srcIdx[p2] = r4.z; enorm[p2] = dr2 * dc2;
        srcIdx[p3] = r4.w; enorm[p3] = dr3 * dc3;
    } else {
        for (int e = e4; e < E; e++) {
            int r = row[e], c = col[e];
            int pos = atomicAdd(&cursor[c], 1);
            srcIdx[pos] = r;
            enorm[pos]  = dis[r] * dis[c];
        }
    }
}

// ---------------- folded BN scale/shift precompute (for SpMM epilogues) ----
__global__ void ss_all_kernel(const float* __restrict__ b1c, const float* __restrict__ g1,
                              const float* __restrict__ b1, const float* __restrict__ m1,
                              const float* __restrict__ v1,
                              const float* __restrict__ b2c, const float* __restrict__ g2,
                              const float* __restrict__ b2, const float* __restrict__ m2,
                              const float* __restrict__ v2,
                              const float* __restrict__ b3c, const float* __restrict__ g3,
                              const float* __restrict__ b3, const float* __restrict__ m3,
                              const float* __restrict__ v3,
                              float* __restrict__ sc, float* __restrict__ sh) {
    int L = blockIdx.x;
    int c = threadIdx.x;
    if (c >= H3) return;
    const float* cb = (L == 0) ? b1c : (L == 1) ? b2c : b3c;
    const float* g  = (L == 0) ? g1  : (L == 1) ? g2  : g3;
    const float* b  = (L == 0) ? b1  : (L == 1) ? b2  : b3;
    const float* m  = (L == 0) ? m1  : (L == 1) ? m2  : m3;
    const float* v  = (L == 0) ? v1  : (L == 1) ? v2  : v3;
    float s = g[c] * rsqrtf(v[c] + BN_EPS);
    sc[L * H3 + c] = s;
    sh[L * H3 + c] = (cb[c] - m[c]) * s + b[c];
}

// ---------------- fp16 gather helpers ----------------
__device__ __forceinline__ float4 h4_to_f4(uint2 raw) {
    __half2 p0 = *reinterpret_cast<__half2*>(&raw.x);
    __half2 p1 = *reinterpret_cast<__half2*>(&raw.y);
    float2 f0 = __half22float2(p0);
    float2 f1 = __half22float2(p1);
    return make_float4(f0.x, f0.y, f1.x, f1.y);
}

__device__ __forceinline__ uint2 f4_to_h4(float4 v) {
    __half2 p0 = __floats2half2_rn(v.x, v.y);
    __half2 p1 = __floats2half2_rn(v.z, v.w);
    uint2 r;
    r.x = *reinterpret_cast<unsigned*>(&p0);
    r.y = *reinterpret_cast<unsigned*>(&p1);
    return r;
}

// ---------------- SpMM hop 1: 120-wide fp16 gather, idx prefetch pipeline ----
__global__ void __launch_bounds__(256)
spmm_h1(const uint2* __restrict__ Zr2, float4* __restrict__ H, uint2* __restrict__ Zs2,
        const int* __restrict__ ptr, const int* __restrict__ srcIdx,
        const float* __restrict__ enorm, const float* __restrict__ dis,
        const float* __restrict__ ssS, const float* __restrict__ ssH, int N) {
    const int lane = threadIdx.x & 31;
    const int node = blockIdx.x * 8 + (threadIdx.x >> 5);
    if (node >= N) return;
    const bool act = lane < 30;

    float d = dis[node];
    float dd = d * d;
    float4 acc = make_float4(0.f, 0.f, 0.f, 0.f);
    if (act) {
        float4 v = h4_to_f4(Zr2[node * 30 + lane]);
        acc.x = dd * v.x; acc.y = dd * v.y; acc.z = dd * v.z; acc.w = dd * v.w;
    }

    int s = ptr[node], e = ptr[node + 1];
    int k = s;
    int i0 = 0, i1 = 0, i2 = 0, i3 = 0;
    float w0 = 0.f, w1 = 0.f, w2 = 0.f, w3 = 0.f;
    if (k + 3 < e) {
        i0 = srcIdx[k]; i1 = srcIdx[k + 1]; i2 = srcIdx[k + 2]; i3 = srcIdx[k + 3];
        w0 = enorm[k]; w1 = enorm[k + 1]; w2 = enorm[k + 2]; w3 = enorm[k + 3];
    }
    while (k + 3 < e) {
        int kn = k + 4;
        int p0 = 0, p1 = 0, p2 = 0, p3 = 0;
        float q0 = 0.f, q1 = 0.f, q2 = 0.f, q3 = 0.f;
        if (kn + 3 < e) {       // prefetch next batch before dependent gathers
            p0 = srcIdx[kn]; p1 = srcIdx[kn + 1]; p2 = srcIdx[kn + 2]; p3 = srcIdx[kn + 3];
            q0 = enorm[kn]; q1 = enorm[kn + 1]; q2 = enorm[kn + 2]; q3 = enorm[kn + 3];
        }
        if (act) {
            float4 v0 = h4_to_f4(Zr2[i0 * 30 + lane]);
            float4 v1 = h4_to_f4(Zr2[i1 * 30 + lane]);
            float4 v2 = h4_to_f4(Zr2[i2 * 30 + lane]);
            float4 v3 = h4_to_f4(Zr2[i3 * 30 + lane]);
            acc.x += w0 * v0.x; acc.y += w0 * v0.y; acc.z += w0 * v0.z; acc.w += w0 * v0.w;
            acc.x += w1 * v1.x; acc.y += w1 * v1.y; acc.z += w1 * v1.z; acc.w += w1 * v1.w;
            acc.x += w2 * v2.x; acc.y += w2 * v2.y; acc.z += w2 * v2.z; acc.w += w2 * v2.w;
            acc.x += w3 * v3.x; acc.y += w3 * v3.y; acc.z += w3 * v3.z; acc.w += w3 * v3.w;
        }
        i0 = p0; i1 = p1; i2 = p2; i3 = p3;
        w0 = q0; w1 = q1; w2 = q2; w3 = q3;
        k = kn;
    }
    for (; k < e; k++) {
        int sx = srcIdx[k];
        float wx = enorm[k];
        if (act) {
            float4 v0 = h4_to_f4(Zr2[sx * 30 + lane]);
            acc.x += wx * v0.x; acc.y += wx * v0.y; acc.z += wx * v0.z; acc.w += wx * v0.w;
        }
    }

    if (lane < 15) {
        float4 sc = reinterpret_cast<const float4*>(ssS)[lane];
        float4 sh = reinterpret_cast<const float4*>(ssH)[lane];
        float4 o;
        o.x = acc.x * sc.x + sh.x;
        o.y = acc.y * sc.y + sh.y;
        o.z = acc.z * sc.z + sh.z;
        o.w = acc.w * sc.w + sh.w;
        H[node * 45 + 15 + lane] = o;                // H[:, 60:120] fp32
    } else if (act) {
        Zs2[node * 15 + (lane - 15)] = f4_to_h4(acc); // raw p=2 hop-1 fp16
    }
}

// ---------------- SpMM hop 2: 60-wide fp16 gather, idx prefetch pipeline ----
__global__ void __launch_bounds__(256)
spmm_h2(const uint2* __restrict__ Zs2, float4* __restrict__ H,
        const int* __restrict__ ptr, const int* __restrict__ srcIdx,
        const float* __restrict__ enorm, const float* __restrict__ dis,
        const float* __restrict__ ssS, const float* __restrict__ ssH, int N) {
    const int l = threadIdx.x & 15;
    const int node = blockIdx.x * 16 + (threadIdx.x >> 4);
    if (node >= N) return;
    const bool act = l < 15;

    float d = dis[node];
    float dd = d * d;
    float4 acc = make_float4(0.f, 0.f, 0.f, 0.f);
    if (act) {
        float4 v = h4_to_f4(Zs2[node * 15 + l]);
        acc.x = dd * v.x; acc.y = dd * v.y; acc.z = dd * v.z; acc.w = dd * v.w;
    }

    int s = ptr[node], e = ptr[node + 1];
    int k = s;
    int i0 = 0, i1 = 0, i2 = 0, i3 = 0;
    float w0 = 0.f, w1 = 0.f, w2 = 0.f, w3 = 0.f;
    if (k + 3 < e) {
        i0 = srcIdx[k]; i1 = srcIdx[k + 1]; i2 = srcIdx[k + 2]; i3 = srcIdx[k + 3];
        w0 = enorm[k]; w1 = enorm[k + 1]; w2 = enorm[k + 2]; w3 = enorm[k + 3];
    }
    while (k + 3 < e) {
        int kn = k + 4;
        int p0 = 0, p1 = 0, p2 = 0, p3 = 0;
        float q0 = 0.f, q1 = 0.f, q2 = 0.f, q3 = 0.f;
        if (kn + 3 < e) {
            p0 = srcIdx[kn]; p1 = srcIdx[kn + 1]; p2 = srcIdx[kn + 2]; p3 = srcIdx[kn + 3];
            q0 = enorm[kn]; q1 = enorm[kn + 1]; q2 = enorm[kn + 2]; q3 = enorm[kn + 3];
        }
        if (act) {
            float4 v0 = h4_to_f4(Zs2[i0 * 15 + l]);
            float4 v1 = h4_to_f4(Zs2[i1 * 15 + l]);
            float4 v2 = h4_to_f4(Zs2[i2 * 15 + l]);
            float4 v3 = h4_to_f4(Zs2[i3 * 15 + l]);
            acc.x += w0 * v0.x; acc.y += w0 * v0.y; acc.z += w0 * v0.z; acc.w += w0 * v0.w;
            acc.x += w1 * v1.x; acc.y += w1 * v1.y; acc.z += w1 * v1.z; acc.w += w1 * v1.w;
            acc.x += w2 * v2.x; acc.y += w2 * v2.y; acc.z += w2 * v2.z; acc.w += w2 * v2.w;
            acc.x += w3 * v3.x; acc.y += w3 * v3.y; acc.z += w3 * v3.z; acc.w += w3 * v3.w;
        }
        i0 = p0; i1 = p1; i2 = p2; i3 = p3;
        w0 = q0; w1 = q1; w2 = q2; w3 = q3;
        k = kn;
    }
    for (; k < e; k++) {
        int sx = srcIdx[k];
        float wx = enorm[k];
        if (act) {
            float4 v0 = h4_to_f4(Zs2[sx * 15 + l]);
            acc.x += wx * v0.x; acc.y += wx * v0.y; acc.z += wx * v0.z; acc.w += wx * v0.w;
        }
    }

    if (act) {
        float4 sc = reinterpret_cast<const float4*>(ssS)[l];
        float4 sh = reinterpret_cast<const float4*>(ssH)[l];
        float4 o;
        o.x = acc.x * sc.x + sh.x;
        o.y = acc.y * sc.y + sh.y;
        o.z = acc.z * sc.z + sh.z;
        o.w = acc.w * sc.w + sh.w;
        H[node * 45 + 30 + l] = o;          // H[:, 120:180] fp32
    }
}

// ---------------- bf16 split helpers ----------------
__device__ __forceinline__ unsigned pk_bf2(float x, float y) {
    __nv_bfloat162 p = __floats2bfloat162_rn(x, y);
    return *reinterpret_cast<unsigned*>(&p);
}

__device__ __forceinline__ void mma_bf16(float* d, unsigned a0, unsigned a1,
                                         unsigned a2, unsigned a3,
                                         unsigned b0, unsigned b1) {
    asm volatile("mma.sync.aligned.m16n8k16.row.col.f32.bf16.bf16.f32 "
                 "{%0,%1,%2,%3}, {%4,%5,%6,%7}, {%8,%9}, {%0,%1,%2,%3};"
                 : "+f"(d[0]), "+f"(d[1]), "+f"(d[2]), "+f"(d[3])
                 : "r"(a0), "r"(a1), "r"(a2), "r"(a3), "r"(b0), "r"(b1));
}

template <int ITERS, int THREADS>
__device__ __forceinline__ void ldg_tile(const float* __restrict__ base, int row0,
                                         int rows_max, int K, int kb, int tid,
                                         float2 v[ITERS]) {
    #pragma unroll
    for (int it = 0; it < ITERS; it++) {
        int idx = tid + it * THREADS;
        int r = idx >> 4, j = idx & 15;
        int gr = row0 + r, gk = kb + 2 * j;
        v[it] = (gr < rows_max && gk < K)
                ? *reinterpret_cast<const float2*>(&base[(size_t)gr * K + gk])
                : make_float2(0.f, 0.f);
    }
}

template <int ITERS, int THREADS>
__device__ __forceinline__ void sts_tile(unsigned* buf, int tid, const float2 v[ITERS]) {
    #pragma unroll
    for (int it = 0; it < ITERS; it++) {
        int idx = tid + it * THREADS;
        int r = idx >> 4, j = idx & 15;
        float2 a = v[it];
        __nv_bfloat16 hx = __float2bfloat16_rn(a.x);
        __nv_bfloat16 hy = __float2bfloat16_rn(a.y);
        float mx = a.x - __bfloat162float(hx);
        float my = a.y - __bfloat162float(hy);
        __nv_bfloat162 hp; hp.x = hx; hp.y = hy;
        unsigned hi = *reinterpret_cast<unsigned*>(&hp);
        unsigned mid = pk_bf2(mx, my);
        *reinterpret_cast<uint2*>(&buf[r * 36 + 2 * j]) = make_uint2(hi, mid);
    }
}

// ---------------- fused conv GEMM: A[N x K] @ Wall[180 x K]^T, 128x192 tile ----
// cols 0:60 -> fp32 finalized Hdst[:,0:60] (BN scale/shift computed in prologue
// from raw params -> no ss dependency); cols 60:180 -> fp16 raw Zr.
#define FUSED_SMEM_BYTES ((2 * 128 * 36 + 2 * 192 * 36) * 4)

__global__ void __launch_bounds__(512, 1)
gemm_conv_fused(const float* __restrict__ A, const float* __restrict__ Wall,
                const float* __restrict__ bng, const float* __restrict__ bnb,
                const float* __restrict__ bnm, const float* __restrict__ bnv,
                const float* __restrict__ convb,
                float* __restrict__ Hdst, __half2* __restrict__ Zr, int N, int K) {
    extern __shared__ unsigned smem_u[];
    unsigned* sA = smem_u;                    // [2][128][36]
    unsigned* sW = smem_u + 2 * 128 * 36;     // [2][192][36]
    __shared__ float sSc[60], sSh[60];

    const int tid  = threadIdx.x;
    const int lane = tid & 31;
    const int wid  = tid >> 5;
    const int warpM = wid & 3;
    const int warpN = wid >> 2;
    const int row0 = blockIdx.x * 128;
    const int g = lane >> 2;
    const int t = lane & 3;
    const int mBase = warpM * 32;

    // prologue: per-block BN fold for the 60 finalized columns
    if (tid < 60) {
        float s = bng[tid] * rsqrtf(bnv[tid] + BN_EPS);
        sSc[tid] = s;
        sSh[tid] = (convb[tid] - bnm[tid]) * s + bnb[tid];
    }

    float acc[2][6][4];
    #pragma unroll
    for (int mt = 0; mt < 2; mt++)
        #pragma unroll
        for (int nt = 0; nt < 6; nt++)
            #pragma unroll
            for (int j = 0; j < 4; j++) acc[mt][nt][j] = 0.0f;

    float2 aReg[4], wReg[6];
    ldg_tile<4, 512>(A, row0, N, K, 0, tid, aReg);
    ldg_tile<6, 512>(Wall, 0, H3, K, 0, tid, wReg);
    sts_tile<4, 512>(sA, tid, aReg);
    sts_tile<6, 512>(sW, tid, wReg);
    __syncthreads();

    const int nC = (K + 31) / 32;
    for (int c = 0; c < nC; c++) {
        const int cur = c & 1;
        const unsigned* cA = sA + cur * 128 * 36;
        const unsigned* cW = sW + cur * 192 * 36;
        if (c + 1 < nC) {
            ldg_tile<4, 512>(A, row0, N, K, (c + 1) * 32, tid, aReg);
            ldg_tile<6, 512>(Wall, 0, H3, K, (c + 1) * 32, tid, wReg);
        }
        #pragma unroll
        for (int ks = 0; ks < 2; ks++) {
            const int pb = 2 * (8 * ks + t);
            uint2 aF[2][4];
            #pragma unroll
            for (int mt = 0; mt < 2; mt++) {
                const int br = mBase + mt * 16 + g;
                aF[mt][0] = *reinterpret_cast<const uint2*>(&cA[br * 36 + pb]);
                aF[mt][1] = *reinterpret_cast<const uint2*>(&cA[(br + 8) * 36 + pb]);
                aF[mt][2] = *reinterpret_cast<const uint2*>(&cA[br * 36 + pb + 8]);
                aF[mt][3] = *reinterpret_cast<const uint2*>(&cA[(br + 8) * 36 + pb + 8]);
            }
            #pragma unroll
            for (int nt = 0; nt < 6; nt++) {
                const int bn_ = warpN * 48 + nt * 8 + g;
                uint2 b0 = *reinterpret_cast<const uint2*>(&cW[bn_ * 36 + pb]);
                uint2 b1 = *reinterpret_cast<const uint2*>(&cW[bn_ * 36 + pb + 8]);
                #pragma unroll
                for (int mt = 0; mt < 2; mt++) {
                    mma_bf16(acc[mt][nt], aF[mt][0].x, aF[mt][1].x, aF[mt][2].x, aF[mt][3].x, b0.x, b1.x); // hi*hi
                    mma_bf16(acc[mt][nt], aF[mt][0].x, aF[mt][1].x, aF[mt][2].x, aF[mt][3].x, b0.y, b1.y); // hi*mid
                    mma_bf16(acc[mt][nt], aF[mt][0].y, aF[mt][1].y, aF[mt][2].y, aF[mt][3].y, b0.x, b1.x); // mid*hi
                }
            }
        }
        if (c + 1 < nC) {
            sts_tile<4, 512>(sA + ((c + 1) & 1) * 128 * 36, tid, aReg);
            sts_tile<6, 512>(sW + ((c + 1) & 1) * 192 * 36, tid, wReg);
        }
        __syncthreads();
    }

    #pragma unroll
    for (int mt = 0; mt < 2; mt++) {
        const int rlo = row0 + mBase + mt * 16 + g;
        #pragma unroll
        for (int nt = 0; nt < 6; nt++) {
            const int c0 = warpN * 48 + nt * 8 + 2 * t;   // even; pair (c0, c0+1)
            if (c0 >= H3) continue;
            if (c0 < 60) {
                #pragma unroll
                for (int jj = 0; jj < 2; jj++) {
                    int c = c0 + jj;
                    float sc = sSc[c], sh = sSh[c];
                    if (rlo < N)     Hdst[(size_t)rlo * H3 + c] = acc[mt][nt][jj] * sc + sh;
                    if (rlo + 8 < N) Hdst[(size_t)(rlo + 8) * H3 + c] = acc[mt][nt][2 + jj] * sc + sh;
                }
            } else {
                int zc = (c0 - 60) >> 1;   // half2 index, 60 per row
                __half2 h0 = __floats2half2_rn(acc[mt][nt][0], acc[mt][nt][1]);
                __half2 h1 = __floats2half2_rn(acc[mt][nt][2], acc[mt][nt][3]);
                if (rlo < N)     Zr[(size_t)rlo * 60 + zc] = h0;
                if (rlo + 8 < N) Zr[(size_t)(rlo + 8) * 60 + zc] = h1;
            }
        }
    }
}

// ---------------- final linear GEMM (128x64 tile, bias only) ----------------
#define GEMM_SMEM_BYTES ((2 * 128 * 36 + 2 * 64 * 36) * 4)

__global__ void __launch_bounds__(256, 2)
gemm_final(const float* __restrict__ A, const float* __restrict__ W,
           const float* __restrict__ bias, float* __restrict__ outF, int N, int K, int Cc) {
    extern __shared__ unsigned smem_u[];
    unsigned* sA = smem_u;                    // [2][128][36]
    unsigned* sW = smem_u + 2 * 128 * 36;     // [2][64][36]

    const int tid  = threadIdx.x;
    const int lane = tid & 31;
    const int wid  = tid >> 5;
    const int warpM = wid & 3;
    const int warpN = wid >> 2;
    const int row0 = blockIdx.x * 128;
    const int g = lane >> 2;
    const int t = lane & 3;
    const int mBase = warpM * 32;

    float acc[2][4][4];
    #pragma unroll
    for (int mt = 0; mt < 2; mt++)
        #pragma unroll
        for (int nt = 0; nt < 4; nt++)
            #pragma unroll
            for (int j = 0; j < 4; j++) acc[mt][nt][j] = 0.0f;

    float2 aReg[8], wReg[4];
    ldg_tile<8, 256>(A, row0, N, K, 0, tid, aReg);
    ldg_tile<4, 256>(W, 0, Cc, K, 0, tid, wReg);
    sts_tile<8, 256>(sA, tid, aReg);
    sts_tile<4, 256>(sW, tid, wReg);
    __syncthreads();

    const int nC = (K + 31) / 32;
    for (int c = 0; c < nC; c++) {
        const int cur = c & 1;
        const unsigned* cA = sA + cur * 128 * 36;
        const unsigned* cW = sW + cur * 64 * 36;
        if (c + 1 < nC) {
            ldg_tile<8, 256>(A, row0, N, K, (c + 1) * 32, tid, aReg);
            ldg_tile<4, 256>(W, 0, Cc, K, (c + 1) * 32, tid, wReg);
        }
        #pragma unroll
        for (int ks = 0; ks < 2; ks++) {
            const int pb = 2 * (8 * ks + t);
            uint2 aF[2][4];
            #pragma unroll
            for (int mt = 0; mt < 2; mt++) {
                const int br = mBase + mt * 16 + g;
                aF[mt][0] = *reinterpret_cast<const uint2*>(&cA[br * 36 + pb]);
                aF[mt][1] = *reinterpret_cast<const uint2*>(&cA[(br + 8) * 36 + pb]);
                aF[mt][2] = *reinterpret_cast<const uint2*>(&cA[br * 36 + pb + 8]);
                aF[mt][3] = *reinterpret_cast<const uint2*>(&cA[(br + 8) * 36 + pb + 8]);
            }
            #pragma unroll
            for (int nt = 0; nt < 4; nt++) {
                const int bn_ = warpN * 32 + nt * 8 + g;
                uint2 b0 = *reinterpret_cast<const uint2*>(&cW[bn_ * 36 + pb]);
                uint2 b1 = *reinterpret_cast<const uint2*>(&cW[bn_ * 36 + pb + 8]);
                #pragma unroll
                for (int mt = 0; mt < 2; mt++) {
                    mma_bf16(acc[mt][nt], aF[mt][0].x, aF[mt][1].x, aF[mt][2].x, aF[mt][3].x, b0.x, b1.x);
                    mma_bf16(acc[mt][nt], aF[mt][0].x, aF[mt][1].x, aF[mt][2].x, aF[mt][3].x, b0.y, b1.y);
                    mma_bf16(acc[mt][nt], aF[mt][0].y, aF[mt][1].y, aF[mt][2].y, aF[mt][3].y, b0.x, b1.x);
                }
            }
        }
        if (c + 1 < nC) {
            sts_tile<8, 256>(sA + ((c + 1) & 1) * 128 * 36, tid, aReg);
            sts_tile<4, 256>(sW + ((c + 1) & 1) * 64 * 36, tid, wReg);
        }
        __syncthreads();
    }

    #pragma unroll
    for (int mt = 0; mt < 2; mt++) {
        const int rlo = row0 + mBase + mt * 16 + g;
        #pragma unroll
        for (int nt = 0; nt < 4; nt++) {
            const int cb = warpN * 32 + nt * 8 + 2 * t;
            #pragma unroll
            for (int jj = 0; jj < 2; jj++) {
                int c = cb + jj;
                if (c >= Cc) continue;
                float add = bias[c];
                if (rlo < N)     outF[(size_t)rlo * CC + c] = acc[mt][nt][jj] + add;
                if (rlo + 8 < N) outF[(size_t)(rlo + 8) * CC + c] = acc[mt][nt][2 + jj] + add;
            }
        }
    }
}

// ---------------- host launch ----------------
extern "C" void kernel_launch(void* const* d_in, const int* in_sizes, int n_in,
                              void* d_out, int out_size) {
    const float* x       = (const float*)d_in[0];
    const int*   ei      = (const int*)d_in[1];
    const float* conv1_W = (const float*)d_in[2];
    const float* conv1_b = (const float*)d_in[3];
    const float* conv2_W = (const float*)d_in[4];
    const float* conv2_b = (const float*)d_in[5];
    const float* conv3_W = (const float*)d_in[6];
    const float* conv3_b = (const float*)d_in[7];
    const float* bn1_g = (const float*)d_in[8];
    const float* bn1_b = (const float*)d_in[9];
    const float* bn1_m = (const float*)d_in[10];
    const float* bn1_v = (const float*)d_in[11];
    const float* bn2_g = (const float*)d_in[12];
    const float* bn2_b = (const float*)d_in[13];
    const float* bn2_m = (const float*)d_in[14];
    const float* bn2_v = (const float*)d_in[15];
    const float* bn3_g = (const float*)d_in[16];
    const float* bn3_b = (const float*)d_in[17];
    const float* bn3_m = (const float*)d_in[18];
    const float* bn3_v = (const float*)d_in[19];
    const float* lin_W = (const float*)d_in[20];
    const float* lin_b = (const float*)d_in[21];
    float* out = (float*)d_out;

    const int N = in_sizes[0] / DD;
    const int E = in_sizes[1] / 2;

    float *Ha, *Hb, *enorm, *dis, *sc, *sh;
    __half *Zr16, *Zs16;
    int *cnt, *ptr, *cursor, *srcIdx, *blockSum;
    cudaGetSymbolAddress((void**)&Zr16, g_Zr16);
    cudaGetSymbolAddress((void**)&Zs16, g_Zs16);
    cudaGetSymbolAddress((void**)&Ha, g_Ha);
    cudaGetSymbolAddress((void**)&Hb, g_Hb);
    cudaGetSymbolAddress((void**)&sc, g_scale);
    cudaGetSymbolAddress((void**)&sh, g_shift);
    cudaGetSymbolAddress((void**)&cnt, g_cnt);
    cudaGetSymbolAddress((void**)&ptr, g_ptr);
    cudaGetSymbolAddress((void**)&cursor, g_cursor);
    cudaGetSymbolAddress((void**)&srcIdx, g_srcIdx);
    cudaGetSymbolAddress((void**)&enorm, g_enorm);
    cudaGetSymbolAddress((void**)&dis, g_dis);
    cudaGetSymbolAddress((void**)&blockSum, g_blockSum);

    cudaFuncSetAttribute(gemm_conv_fused,
                         cudaFuncAttributeMaxDynamicSharedMemorySize, FUSED_SMEM_BYTES);
    cudaFuncSetAttribute(gemm_final,
                         cudaFuncAttributeMaxDynamicSharedMemorySize, GEMM_SMEM_BYTES);

    // side stream + fork/join events (created once, pre-capture)
    static cudaStream_t s2 = nullptr;
    static cudaEvent_t evFork = nullptr, evCsr = nullptr;
    if (s2 == nullptr) {
        cudaStreamCreateWithFlags(&s2, cudaStreamNonBlocking);
        cudaEventCreateWithFlags(&evFork, cudaEventDisableTiming);
        cudaEventCreateWithFlags(&evCsr, cudaEventDisableTiming);
    }

    const int* e_row = ei;
    const int* e_col = ei + E;
    const int nScanBlocks = (N + 255) / 256;
    const int edgeBlocks = (E / 4 + 255) / 256;

    // ---- fork: ss + CSR build on s2, layer-1 GEMM on default stream ----
    cudaEventRecord(evFork, 0);
    cudaStreamWaitEvent(s2, evFork, 0);

    ss_all_kernel<<<3, H3, 0, s2>>>(conv1_b, bn1_g, bn1_b, bn1_m, bn1_v,
                                    conv2_b, bn2_g, bn2_b, bn2_m, bn2_v,
                                    conv3_b, bn3_g, bn3_b, bn3_m, bn3_v, sc, sh);
    hist_kernel<<<edgeBlocks, 256, 0, s2>>>(e_col, cnt, E);
    partial_kernel<<<nScanBlocks, 256, 0, s2>>>(cnt, blockSum, N);
    scanwrite_kernel<<<nScanBlocks, 256, 0, s2>>>(cnt, blockSum, ptr, cursor, dis, N, nScanBlocks);
    scatter_kernel<<<edgeBlocks, 256, 0, s2>>>(e_row, e_col, dis, cursor, srcIdx, enorm, E);
    cudaEventRecord(evCsr, s2);

    const int gemmBlocks = (N + 127) / 128;
    const int h1Blocks = (N + 7) / 8;
    const int h2Blocks = (N + 15) / 16;

    // default stream: layer-1 projection GEMM starts immediately
    gemm_conv_fused<<<gemmBlocks, 512, FUSED_SMEM_BYTES>>>(x, conv1_W,
                                                           bn1_g, bn1_b, bn1_m, bn1_v, conv1_b,
                                                           Ha, (__half2*)Zr16, N, DD);

    // ---- join: SpMM needs CSR + ss ----
    cudaStreamWaitEvent(0, evCsr, 0);

    // ---- layer 1 aggregation ----
    spmm_h1<<<h1Blocks, 256>>>((const uint2*)Zr16, (float4*)Ha, (uint2*)Zs16,
                               ptr, srcIdx, enorm, dis, sc + 60, sh + 60, N);
    spmm_h2<<<h2Blocks, 256>>>((const uint2*)Zs16, (float4*)Ha,
                               ptr, srcIdx, enorm, dis, sc + 120, sh + 120, N);

    // ---- layer 2 (K=180) ----
    gemm_conv_fused<<<gemmBlocks, 512, FUSED_SMEM_BYTES>>>(Ha, conv2_W,
                                                           bn2_g, bn2_b, bn2_m, bn2_v, conv2_b,
                                                           Hb, (__half2*)Zr16, N, H3);
    spmm_h1<<<h1Blocks, 256>>>((const uint2*)Zr16, (float4*)Hb, (uint2*)Zs16,
                               ptr, srcIdx, enorm, dis, sc + H3 + 60, sh + H3 + 60, N);
    spmm_h2<<<h2Blocks, 256>>>((const uint2*)Zs16, (float4*)Hb,
                               ptr, srcIdx, enorm, dis, sc + H3 + 120, sh + H3 + 120, N);

    // ---- layer 3 (K=180) ----
    gemm_conv_fused<<<gemmBlocks, 512, FUSED_SMEM_BYTES>>>(Hb, conv3_W,
                                                           bn3_g, bn3_b, bn3_m, bn3_v, conv3_b,
                                                           Ha, (__half2*)Zr16, N, H3);
    spmm_h1<<<h1Blocks, 256>>>((const uint2*)Zr16, (float4*)Ha, (uint2*)Zs16,
                               ptr, srcIdx, enorm, dis, sc + 2 * H3 + 60, sh + 2 * H3 + 60, N);
    spmm_h2<<<h2Blocks, 256>>>((const uint2*)Zs16, (float4*)Ha,
                               ptr, srcIdx, enorm, dis, sc + 2 * H3 + 120, sh + 2 * H3 + 120, N);

    // ---- final linear ----
    gemm_final<<<gemmBlocks, 256, GEMM_SMEM_BYTES>>>(Ha, lin_W, lin_b, out, N, H3, CC);
}

// round 16
// speedup vs baseline: 1.0594x; 1.0594x over previous
#include <cuda_runtime.h>
#include <cuda_bf16.h>
#include <cuda_fp16.h>

// ---------------- problem constants ----------------
#define NN 50000
#define EE 400000
#define DD 128
#define HH 60
#define H3 180
#define CC 40
#define BN_EPS 1e-5f

// ---------------- static scratch ----------------
__device__ __half g_Zr16[NN * 120];   // raw p=1,2 projections (fp16)
__device__ __half g_Zs16[NN * 64];    // raw hop-1 result for p=2 (fp16)
__device__ float g_Ha[NN * H3];
__device__ float g_Hb[NN * H3];
__device__ float g_scale[3 * H3];
__device__ float g_shift[3 * H3];
__device__ int   g_cnt[NN];           // zero-init; re-zeroed by scanwrite each call
__device__ int   g_ptr[NN + 1];
__device__ int   g_cursor[NN];
__device__ int   g_blockSum[256];
__device__ int   g_srcIdx[EE];
__device__ float g_enorm[EE];
__device__ float g_dis[NN];

// ---------------- CSR build (scalar, 1 edge/thread — R12 proven) ----------------
__global__ void hist_kernel(const int* __restrict__ col, int* __restrict__ cnt, int E) {
    int e = blockIdx.x * blockDim.x + threadIdx.x;
    if (e < E) atomicAdd(&cnt[col[e]], 1);
}

// per-256-block sums of cnt
__global__ void partial_kernel(const int* __restrict__ cnt, int* __restrict__ blockSum, int n) {
    __shared__ int ws[8];
    int i = blockIdx.x * 256 + threadIdx.x;
    int lane = threadIdx.x & 31, wid = threadIdx.x >> 5;
    int v = (i < n) ? cnt[i] : 0;
    #pragma unroll
    for (int off = 16; off > 0; off >>= 1) v += __shfl_down_sync(0xffffffffu, v, off);
    if (lane == 0) ws[wid] = v;
    __syncthreads();
    if (wid == 0) {
        int s = (lane < 8) ? ws[lane] : 0;
        #pragma unroll
        for (int off = 4; off > 0; off >>= 1) s += __shfl_down_sync(0xffffffffu, s, off);
        if (lane == 0) blockSum[blockIdx.x] = s;
    }
}

// fused: scan blockSum (redundantly per block), then per-chunk scan,
// write ptr/cursor/dis, and zero cnt for the next call/replay.
__global__ void scanwrite_kernel(int* __restrict__ cnt, const int* __restrict__ blockSum,
                                 int* __restrict__ ptr, int* __restrict__ cursor,
                                 float* __restrict__ dis, int n, int nBlocks) {
    __shared__ int ws[8];
    __shared__ int sOff[256];
    const int tid = threadIdx.x, lane = tid & 31, wid = tid >> 5;

    // phase A: exclusive scan of blockSum[0..nBlocks) into sOff
    int bv = (tid < nBlocks) ? blockSum[tid] : 0;
    int bx = bv;
    #pragma unroll
    for (int off = 1; off < 32; off <<= 1) {
        int t = __shfl_up_sync(0xffffffffu, bx, off);
        if (lane >= off) bx += t;
    }
    if (lane == 31) ws[wid] = bx;
    __syncthreads();
    if (wid == 0 && lane < 8) {
        int w = ws[lane];
        #pragma unroll
        for (int off = 1; off < 8; off <<= 1) {
            int t = __shfl_up_sync(0xffu, w, off);
            if (lane >= off) w += t;
        }
        ws[lane] = w;
    }
    __syncthreads();
    {
        int bwoff = wid ? ws[wid - 1] : 0;
        sOff[tid] = bwoff + bx - bv;
    }
    __syncthreads();
    const int myOff = sOff[blockIdx.x];
    __syncthreads();   // ws reused below

    // phase B: per-chunk scan
    int i = blockIdx.x * 256 + tid;
    int v = (i < n) ? cnt[i] : 0;
    int x = v;
    #pragma unroll
    for (int off = 1; off < 32; off <<= 1) {
        int t = __shfl_up_sync(0xffffffffu, x, off);
        if (lane >= off) x += t;
    }
    if (lane == 31) ws[wid] = x;
    __syncthreads();
    if (wid == 0 && lane < 8) {
        int w = ws[lane];
        #pragma unroll
        for (int off = 1; off < 8; off <<= 1) {
            int t = __shfl_up_sync(0xffu, w, off);
            if (lane >= off) w += t;
        }
        ws[lane] = w;
    }
    __syncthreads();
    int woff = wid ? ws[wid - 1] : 0;
    int excl = myOff + woff + x - v;
    if (i < n) {
        ptr[i] = excl;
        cursor[i] = excl;
        dis[i] = rsqrtf((float)(v + 1));   // +1 self loop
        if (i == n - 1) ptr[n] = excl + v;
        cnt[i] = 0;                         // reset for next call / replay
    }
}

// scalar, 1 edge/thread — R12 proven
__global__ void scatter_kernel(const int* __restrict__ row, const int* __restrict__ col,
                               const float* __restrict__ dis, int* __restrict__ cursor,
                               int* __restrict__ srcIdx, float* __restrict__ enorm, int E) {
    int e = blockIdx.x * blockDim.x + threadIdx.x;
    if (e < E) {
        int r = row[e], c = col[e];
        int pos = atomicAdd(&cursor[c], 1);
        srcIdx[pos] = r;
        enorm[pos]  = dis[r] * dis[c];
    }
}

// ---------------- folded BN scale/shift precompute (for SpMM epilogues) ----
__global__ void ss_all_kernel(const float* __restrict__ b1c, const float* __restrict__ g1,
                              const float* __restrict__ b1, const float* __restrict__ m1,
                              const float* __restrict__ v1,
                              const float* __restrict__ b2c, const float* __restrict__ g2,
                              const float* __restrict__ b2, const float* __restrict__ m2,
                              const float* __restrict__ v2,
                              const float* __restrict__ b3c, const float* __restrict__ g3,
                              const float* __restrict__ b3, const float* __restrict__ m3,
                              const float* __restrict__ v3,
                              float* __restrict__ sc, float* __restrict__ sh) {
    int L = blockIdx.x;
    int c = threadIdx.x;
    if (c >= H3) return;
    const float* cb = (L == 0) ? b1c : (L == 1) ? b2c : b3c;
    const float* g  = (L == 0) ? g1  : (L == 1) ? g2  : g3;
    const float* b  = (L == 0) ? b1  : (L == 1) ? b2  : b3;
    const float* m  = (L == 0) ? m1  : (L == 1) ? m2  : m3;
    const float* v  = (L == 0) ? v1  : (L == 1) ? v2  : v3;
    float s = g[c] * rsqrtf(v[c] + BN_EPS);
    sc[L * H3 + c] = s;
    sh[L * H3 + c] = (cb[c] - m[c]) * s + b[c];
}

// ---------------- fp16 gather helpers ----------------
__device__ __forceinline__ float4 h4_to_f4(uint2 raw) {
    __half2 p0 = *reinterpret_cast<__half2*>(&raw.x);
    __half2 p1 = *reinterpret_cast<__half2*>(&raw.y);
    float2 f0 = __half22float2(p0);
    float2 f1 = __half22float2(p1);
    return make_float4(f0.x, f0.y, f1.x, f1.y);
}

__device__ __forceinline__ uint2 f4_to_h4(float4 v) {
    __half2 p0 = __floats2half2_rn(v.x, v.y);
    __half2 p1 = __floats2half2_rn(v.z, v.w);
    uint2 r;
    r.x = *reinterpret_cast<unsigned*>(&p0);
    r.y = *reinterpret_cast<unsigned*>(&p1);
    return r;
}

// ---------------- SpMM hop 1: 120-wide fp16 gather (clean 4-edge unroll, R12) ----
__global__ void __launch_bounds__(256)
spmm_h1(const uint2* __restrict__ Zr2, float4* __restrict__ H, uint2* __restrict__ Zs2,
        const int* __restrict__ ptr, const int* __restrict__ srcIdx,
        const float* __restrict__ enorm, const float* __restrict__ dis,
        const float* __restrict__ ssS, const float* __restrict__ ssH, int N) {
    const int lane = threadIdx.x & 31;
    const int node = blockIdx.x * 8 + (threadIdx.x >> 5);
    if (node >= N) return;
    const bool act = lane < 30;

    float d = dis[node];
    float dd = d * d;
    float4 acc = make_float4(0.f, 0.f, 0.f, 0.f);
    if (act) {
        float4 v = h4_to_f4(Zr2[node * 30 + lane]);
        acc.x = dd * v.x; acc.y = dd * v.y; acc.z = dd * v.z; acc.w = dd * v.w;
    }

    int s = ptr[node], e = ptr[node + 1];
    int k = s;
    for (; k + 3 < e; k += 4) {
        int s0 = srcIdx[k], s1 = srcIdx[k + 1], s2 = srcIdx[k + 2], s3 = srcIdx[k + 3];
        float w0 = enorm[k], w1 = enorm[k + 1], w2 = enorm[k + 2], w3 = enorm[k + 3];
        if (act) {
            float4 v0 = h4_to_f4(Zr2[s0 * 30 + lane]);
            float4 v1 = h4_to_f4(Zr2[s1 * 30 + lane]);
            float4 v2 = h4_to_f4(Zr2[s2 * 30 + lane]);
            float4 v3 = h4_to_f4(Zr2[s3 * 30 + lane]);
            acc.x += w0 * v0.x; acc.y += w0 * v0.y; acc.z += w0 * v0.z; acc.w += w0 * v0.w;
            acc.x += w1 * v1.x; acc.y += w1 * v1.y; acc.z += w1 * v1.z; acc.w += w1 * v1.w;
            acc.x += w2 * v2.x; acc.y += w2 * v2.y; acc.z += w2 * v2.z; acc.w += w2 * v2.w;
            acc.x += w3 * v3.x; acc.y += w3 * v3.y; acc.z += w3 * v3.z; acc.w += w3 * v3.w;
        }
    }
    for (; k < e; k++) {
        int s0 = srcIdx[k];
        float w0 = enorm[k];
        if (act) {
            float4 v0 = h4_to_f4(Zr2[s0 * 30 + lane]);
            acc.x += w0 * v0.x; acc.y += w0 * v0.y; acc.z += w0 * v0.z; acc.w += w0 * v0.w;
        }
    }

    if (lane < 15) {
        float4 sc = reinterpret_cast<const float4*>(ssS)[lane];
        float4 sh = reinterpret_cast<const float4*>(ssH)[lane];
        float4 o;
        o.x = acc.x * sc.x + sh.x;
        o.y = acc.y * sc.y + sh.y;
        o.z = acc.z * sc.z + sh.z;
        o.w = acc.w * sc.w + sh.w;
        H[node * 45 + 15 + lane] = o;                // H[:, 60:120] fp32
    } else if (act) {
        Zs2[node * 15 + (lane - 15)] = f4_to_h4(acc); // raw p=2 hop-1 fp16
    }
}

// ---------------- SpMM hop 2: 60-wide fp16 gather (clean 4-edge unroll, R12) ----
__global__ void __launch_bounds__(256)
spmm_h2(const uint2* __restrict__ Zs2, float4* __restrict__ H,
        const int* __restrict__ ptr, const int* __restrict__ srcIdx,
        const float* __restrict__ enorm, const float* __restrict__ dis,
        const float* __restrict__ ssS, const float* __restrict__ ssH, int N) {
    const int l = threadIdx.x & 15;
    const int node = blockIdx.x * 16 + (threadIdx.x >> 4);
    if (node >= N) return;
    const bool act = l < 15;

    float d = dis[node];
    float dd = d * d;
    float4 acc = make_float4(0.f, 0.f, 0.f, 0.f);
    if (act) {
        float4 v = h4_to_f4(Zs2[node * 15 + l]);
        acc.x = dd * v.x; acc.y = dd * v.y; acc.z = dd * v.z; acc.w = dd * v.w;
    }

    int s = ptr[node], e = ptr[node + 1];
    int k = s;
    for (; k + 3 < e; k += 4) {
        int s0 = srcIdx[k], s1 = srcIdx[k + 1], s2 = srcIdx[k + 2], s3 = srcIdx[k + 3];
        float w0 = enorm[k], w1 = enorm[k + 1], w2 = enorm[k + 2], w3 = enorm[k + 3];
        if (act) {
            float4 v0 = h4_to_f4(Zs2[s0 * 15 + l]);
            float4 v1 = h4_to_f4(Zs2[s1 * 15 + l]);
            float4 v2 = h4_to_f4(Zs2[s2 * 15 + l]);
            float4 v3 = h4_to_f4(Zs2[s3 * 15 + l]);
            acc.x += w0 * v0.x; acc.y += w0 * v0.y; acc.z += w0 * v0.z; acc.w += w0 * v0.w;
            acc.x += w1 * v1.x; acc.y += w1 * v1.y; acc.z += w1 * v1.z; acc.w += w1 * v1.w;
            acc.x += w2 * v2.x; acc.y += w2 * v2.y; acc.z += w2 * v2.z; acc.w += w2 * v2.w;
            acc.x += w3 * v3.x; acc.y += w3 * v3.y; acc.z += w3 * v3.z; acc.w += w3 * v3.w;
        }
    }
    for (; k < e; k++) {
        int s0 = srcIdx[k];
        float w0 = enorm[k];
        if (act) {
            float4 v0 = h4_to_f4(Zs2[s0 * 15 + l]);
            acc.x += w0 * v0.x; acc.y += w0 * v0.y; acc.z += w0 * v0.z; acc.w += w0 * v0.w;
        }
    }

    if (act) {
        float4 sc = reinterpret_cast<const float4*>(ssS)[l];
        float4 sh = reinterpret_cast<const float4*>(ssH)[l];
        float4 o;
        o.x = acc.x * sc.x + sh.x;
        o.y = acc.y * sc.y + sh.y;
        o.z = acc.z * sc.z + sh.z;
        o.w = acc.w * sc.w + sh.w;
        H[node * 45 + 30 + l] = o;          // H[:, 120:180] fp32
    }
}

// ---------------- bf16 split helpers ----------------
__device__ __forceinline__ unsigned pk_bf2(float x, float y) {
    __nv_bfloat162 p = __floats2bfloat162_rn(x, y);
    return *reinterpret_cast<unsigned*>(&p);
}

__device__ __forceinline__ void mma_bf16(float* d, unsigned a0, unsigned a1,
                                         unsigned a2, unsigned a3,
                                         unsigned b0, unsigned b1) {
    asm volatile("mma.sync.aligned.m16n8k16.row.col.f32.bf16.bf16.f32 "
                 "{%0,%1,%2,%3}, {%4,%5,%6,%7}, {%8,%9}, {%0,%1,%2,%3};"
                 : "+f"(d[0]), "+f"(d[1]), "+f"(d[2]), "+f"(d[3])
                 : "r"(a0), "r"(a1), "r"(a2), "r"(a3), "r"(b0), "r"(b1));
}

template <int ITERS, int THREADS>
__device__ __forceinline__ void ldg_tile(const float* __restrict__ base, int row0,
                                         int rows_max, int K, int kb, int tid,
                                         float2 v[ITERS]) {
    #pragma unroll
    for (int it = 0; it < ITERS; it++) {
        int idx = tid + it * THREADS;
        int r = idx >> 4, j = idx & 15;
        int gr = row0 + r, gk = kb + 2 * j;
        v[it] = (gr < rows_max && gk < K)
                ? *reinterpret_cast<const float2*>(&base[(size_t)gr * K + gk])
                : make_float2(0.f, 0.f);
    }
}

template <int ITERS, int THREADS>
__device__ __forceinline__ void sts_tile(unsigned* buf, int tid, const float2 v[ITERS]) {
    #pragma unroll
    for (int it = 0; it < ITERS; it++) {
        int idx = tid + it * THREADS;
        int r = idx >> 4, j = idx & 15;
        float2 a = v[it];
        __nv_bfloat16 hx = __float2bfloat16_rn(a.x);
        __nv_bfloat16 hy = __float2bfloat16_rn(a.y);
        float mx = a.x - __bfloat162float(hx);
        float my = a.y - __bfloat162float(hy);
        __nv_bfloat162 hp; hp.x = hx; hp.y = hy;
        unsigned hi = *reinterpret_cast<unsigned*>(&hp);
        unsigned mid = pk_bf2(mx, my);
        *reinterpret_cast<uint2*>(&buf[r * 36 + 2 * j]) = make_uint2(hi, mid);
    }
}

// ---------------- fused conv GEMM: A[N x K] @ Wall[180 x K]^T, 128x192 tile ----
// cols 0:60 -> fp32 finalized Hdst[:,0:60] (BN fold computed in prologue);
// cols 60:180 -> fp16 raw Zr.
#define FUSED_SMEM_BYTES ((2 * 128 * 36 + 2 * 192 * 36) * 4)

__global__ void __launch_bounds__(512, 1)
gemm_conv_fused(const float* __restrict__ A, const float* __restrict__ Wall,
                const float* __restrict__ bng, const float* __restrict__ bnb,
                const float* __restrict__ bnm, const float* __restrict__ bnv,
                const float* __restrict__ convb,
                float* __restrict__ Hdst, __half2* __restrict__ Zr, int N, int K) {
    extern __shared__ unsigned smem_u[];
    unsigned* sA = smem_u;                    // [2][128][36]
    unsigned* sW = smem_u + 2 * 128 * 36;     // [2][192][36]
    __shared__ float sSc[60], sSh[60];

    const int tid  = threadIdx.x;
    const int lane = tid & 31;
    const int wid  = tid >> 5;
    const int warpM = wid & 3;
    const int warpN = wid >> 2;
    const int row0 = blockIdx.x * 128;
    const int g = lane >> 2;
    const int t = lane & 3;
    const int mBase = warpM * 32;

    // prologue: per-block BN fold for the 60 finalized columns
    if (tid < 60) {
        float s = bng[tid] * rsqrtf(bnv[tid] + BN_EPS);
        sSc[tid] = s;
        sSh[tid] = (convb[tid] - bnm[tid]) * s + bnb[tid];
    }

    float acc[2][6][4];
    #pragma unroll
    for (int mt = 0; mt < 2; mt++)
        #pragma unroll
        for (int nt = 0; nt < 6; nt++)
            #pragma unroll
            for (int j = 0; j < 4; j++) acc[mt][nt][j] = 0.0f;

    float2 aReg[4], wReg[6];
    ldg_tile<4, 512>(A, row0, N, K, 0, tid, aReg);
    ldg_tile<6, 512>(Wall, 0, H3, K, 0, tid, wReg);
    sts_tile<4, 512>(sA, tid, aReg);
    sts_tile<6, 512>(sW, tid, wReg);
    __syncthreads();

    const int nC = (K + 31) / 32;
    for (int c = 0; c < nC; c++) {
        const int cur = c & 1;
        const unsigned* cA = sA + cur * 128 * 36;
        const unsigned* cW = sW + cur * 192 * 36;
        if (c + 1 < nC) {
            ldg_tile<4, 512>(A, row0, N, K, (c + 1) * 32, tid, aReg);
            ldg_tile<6, 512>(Wall, 0, H3, K, (c + 1) * 32, tid, wReg);
        }
        #pragma unroll
        for (int ks = 0; ks < 2; ks++) {
            const int pb = 2 * (8 * ks + t);
            uint2 aF[2][4];
            #pragma unroll
            for (int mt = 0; mt < 2; mt++) {
                const int br = mBase + mt * 16 + g;
                aF[mt][0] = *reinterpret_cast<const uint2*>(&cA[br * 36 + pb]);
                aF[mt][1] = *reinterpret_cast<const uint2*>(&cA[(br + 8) * 36 + pb]);
                aF[mt][2] = *reinterpret_cast<const uint2*>(&cA[br * 36 + pb + 8]);
                aF[mt][3] = *reinterpret_cast<const uint2*>(&cA[(br + 8) * 36 + pb + 8]);
            }
            #pragma unroll
            for (int nt = 0; nt < 6; nt++) {
                const int bn_ = warpN * 48 + nt * 8 + g;
                uint2 b0 = *reinterpret_cast<const uint2*>(&cW[bn_ * 36 + pb]);
                uint2 b1 = *reinterpret_cast<const uint2*>(&cW[bn_ * 36 + pb + 8]);
                #pragma unroll
                for (int mt = 0; mt < 2; mt++) {
                    mma_bf16(acc[mt][nt], aF[mt][0].x, aF[mt][1].x, aF[mt][2].x, aF[mt][3].x, b0.x, b1.x); // hi*hi
                    mma_bf16(acc[mt][nt], aF[mt][0].x, aF[mt][1].x, aF[mt][2].x, aF[mt][3].x, b0.y, b1.y); // hi*mid
                    mma_bf16(acc[mt][nt], aF[mt][0].y, aF[mt][1].y, aF[mt][2].y, aF[mt][3].y, b0.x, b1.x); // mid*hi
                }
            }
        }
        if (c + 1 < nC) {
            sts_tile<4, 512>(sA + ((c + 1) & 1) * 128 * 36, tid, aReg);
            sts_tile<6, 512>(sW + ((c + 1) & 1) * 192 * 36, tid, wReg);
        }
        __syncthreads();
    }

    #pragma unroll
    for (int mt = 0; mt < 2; mt++) {
        const int rlo = row0 + mBase + mt * 16 + g;
        #pragma unroll
        for (int nt = 0; nt < 6; nt++) {
            const int c0 = warpN * 48 + nt * 8 + 2 * t;   // even; pair (c0, c0+1)
            if (c0 >= H3) continue;
            if (c0 < 60) {
                #pragma unroll
                for (int jj = 0; jj < 2; jj++) {
                    int c = c0 + jj;
                    float sc = sSc[c], sh = sSh[c];
                    if (rlo < N)     Hdst[(size_t)rlo * H3 + c] = acc[mt][nt][jj] * sc + sh;
                    if (rlo + 8 < N) Hdst[(size_t)(rlo + 8) * H3 + c] = acc[mt][nt][2 + jj] * sc + sh;
                }
            } else {
                int zc = (c0 - 60) >> 1;   // half2 index, 60 per row
                __half2 h0 = __floats2half2_rn(acc[mt][nt][0], acc[mt][nt][1]);
                __half2 h1 = __floats2half2_rn(acc[mt][nt][2], acc[mt][nt][3]);
                if (rlo < N)     Zr[(size_t)rlo * 60 + zc] = h0;
                if (rlo + 8 < N) Zr[(size_t)(rlo + 8) * 60 + zc] = h1;
            }
        }
    }
}

// ---------------- final linear GEMM (128x64 tile, bias only) ----------------
#define GEMM_SMEM_BYTES ((2 * 128 * 36 + 2 * 64 * 36) * 4)

__global__ void __launch_bounds__(256, 2)
gemm_final(const float* __restrict__ A, const float* __restrict__ W,
           const float* __restrict__ bias, float* __restrict__ outF, int N, int K, int Cc) {
    extern __shared__ unsigned smem_u[];
    unsigned* sA = smem_u;                    // [2][128][36]
    unsigned* sW = smem_u + 2 * 128 * 36;     // [2][64][36]

    const int tid  = threadIdx.x;
    const int lane = tid & 31;
    const int wid  = tid >> 5;
    const int warpM = wid & 3;
    const int warpN = wid >> 2;
    const int row0 = blockIdx.x * 128;
    const int g = lane >> 2;
    const int t = lane & 3;
    const int mBase = warpM * 32;

    float acc[2][4][4];
    #pragma unroll
    for (int mt = 0; mt < 2; mt++)
        #pragma unroll
        for (int nt = 0; nt < 4; nt++)
            #pragma unroll
            for (int j = 0; j < 4; j++) acc[mt][nt][j] = 0.0f;

    float2 aReg[8], wReg[4];
    ldg_tile<8, 256>(A, row0, N, K, 0, tid, aReg);
    ldg_tile<4, 256>(W, 0, Cc, K, 0, tid, wReg);
    sts_tile<8, 256>(sA, tid, aReg);
    sts_tile<4, 256>(sW, tid, wReg);
    __syncthreads();

    const int nC = (K + 31) / 32;
    for (int c = 0; c < nC; c++) {
        const int cur = c & 1;
        const unsigned* cA = sA + cur * 128 * 36;
        const unsigned* cW = sW + cur * 64 * 36;
        if (c + 1 < nC) {
            ldg_tile<8, 256>(A, row0, N, K, (c + 1) * 32, tid, aReg);
            ldg_tile<4, 256>(W, 0, Cc, K, (c + 1) * 32, tid, wReg);
        }
        #pragma unroll
        for (int ks = 0; ks < 2; ks++) {
            const int pb = 2 * (8 * ks + t);
            uint2 aF[2][4];
            #pragma unroll
            for (int mt = 0; mt < 2; mt++) {
                const int br = mBase + mt * 16 + g;
                aF[mt][0] = *reinterpret_cast<const uint2*>(&cA[br * 36 + pb]);
                aF[mt][1] = *reinterpret_cast<const uint2*>(&cA[(br + 8) * 36 + pb]);
                aF[mt][2] = *reinterpret_cast<const uint2*>(&cA[br * 36 + pb + 8]);
                aF[mt][3] = *reinterpret_cast<const uint2*>(&cA[(br + 8) * 36 + pb + 8]);
            }
            #pragma unroll
            for (int nt = 0; nt < 4; nt++) {
                const int bn_ = warpN * 32 + nt * 8 + g;
                uint2 b0 = *reinterpret_cast<const uint2*>(&cW[bn_ * 36 + pb]);
                uint2 b1 = *reinterpret_cast<const uint2*>(&cW[bn_ * 36 + pb + 8]);
                #pragma unroll
                for (int mt = 0; mt < 2; mt++) {
                    mma_bf16(acc[mt][nt], aF[mt][0].x, aF[mt][1].x, aF[mt][2].x, aF[mt][3].x, b0.x, b1.x);
                    mma_bf16(acc[mt][nt], aF[mt][0].x, aF[mt][1].x, aF[mt][2].x, aF[mt][3].x, b0.y, b1.y);
                    mma_bf16(acc[mt][nt], aF[mt][0].y, aF[mt][1].y, aF[mt][2].y, aF[mt][3].y, b0.x, b1.x);
                }
            }
        }
        if (c + 1 < nC) {
            sts_tile<8, 256>(sA + ((c + 1) & 1) * 128 * 36, tid, aReg);
            sts_tile<4, 256>(sW + ((c + 1) & 1) * 64 * 36, tid, wReg);
        }
        __syncthreads();
    }

    #pragma unroll
    for (int mt = 0; mt < 2; mt++) {
        const int rlo = row0 + mBase + mt * 16 + g;
        #pragma unroll
        for (int nt = 0; nt < 4; nt++) {
            const int cb = warpN * 32 + nt * 8 + 2 * t;
            #pragma unroll
            for (int jj = 0; jj < 2; jj++) {
                int c = cb + jj;
                if (c >= Cc) continue;
                float add = bias[c];
                if (rlo < N)     outF[(size_t)rlo * CC + c] = acc[mt][nt][jj] + add;
                if (rlo + 8 < N) outF[(size_t)(rlo + 8) * CC + c] = acc[mt][nt][2 + jj] + add;
            }
        }
    }
}

// ---------------- host launch ----------------
extern "C" void kernel_launch(void* const* d_in, const int* in_sizes, int n_in,
                              void* d_out, int out_size) {
    const float* x       = (const float*)d_in[0];
    const int*   ei      = (const int*)d_in[1];
    const float* conv1_W = (const float*)d_in[2];
    const float* conv1_b = (const float*)d_in[3];
    const float* conv2_W = (const float*)d_in[4];
    const float* conv2_b = (const float*)d_in[5];
    const float* conv3_W = (const float*)d_in[6];
    const float* conv3_b = (const float*)d_in[7];
    const float* bn1_g = (const float*)d_in[8];
    const float* bn1_b = (const float*)d_in[9];
    const float* bn1_m = (const float*)d_in[10];
    const float* bn1_v = (const float*)d_in[11];
    const float* bn2_g = (const float*)d_in[12];
    const float* bn2_b = (const float*)d_in[13];
    const float* bn2_m = (const float*)d_in[14];
    const float* bn2_v = (const float*)d_in[15];
    const float* bn3_g = (const float*)d_in[16];
    const float* bn3_b = (const float*)d_in[17];
    const float* bn3_m = (const float*)d_in[18];
    const float* bn3_v = (const float*)d_in[19];
    const float* lin_W = (const float*)d_in[20];
    const float* lin_b = (const float*)d_in[21];
    float* out = (float*)d_out;

    const int N = in_sizes[0] / DD;
    const int E = in_sizes[1] / 2;

    float *Ha, *Hb, *enorm, *dis, *sc, *sh;
    __half *Zr16, *Zs16;
    int *cnt, *ptr, *cursor, *srcIdx, *blockSum;
    cudaGetSymbolAddress((void**)&Zr16, g_Zr16);
    cudaGetSymbolAddress((void**)&Zs16, g_Zs16);
    cudaGetSymbolAddress((void**)&Ha, g_Ha);
    cudaGetSymbolAddress((void**)&Hb, g_Hb);
    cudaGetSymbolAddress((void**)&sc, g_scale);
    cudaGetSymbolAddress((void**)&sh, g_shift);
    cudaGetSymbolAddress((void**)&cnt, g_cnt);
    cudaGetSymbolAddress((void**)&ptr, g_ptr);
    cudaGetSymbolAddress((void**)&cursor, g_cursor);
    cudaGetSymbolAddress((void**)&srcIdx, g_srcIdx);
    cudaGetSymbolAddress((void**)&enorm, g_enorm);
    cudaGetSymbolAddress((void**)&dis, g_dis);
    cudaGetSymbolAddress((void**)&blockSum, g_blockSum);

    cudaFuncSetAttribute(gemm_conv_fused,
                         cudaFuncAttributeMaxDynamicSharedMemorySize, FUSED_SMEM_BYTES);
    cudaFuncSetAttribute(gemm_final,
                         cudaFuncAttributeMaxDynamicSharedMemorySize, GEMM_SMEM_BYTES);

    // side stream + fork/join events (created once, pre-capture)
    static cudaStream_t s2 = nullptr;
    static cudaEvent_t evFork = nullptr, evCsr = nullptr;
    if (s2 == nullptr) {
        cudaStreamCreateWithFlags(&s2, cudaStreamNonBlocking);
        cudaEventCreateWithFlags(&evFork, cudaEventDisableTiming);
        cudaEventCreateWithFlags(&evCsr, cudaEventDisableTiming);
    }

    const int* e_row = ei;
    const int* e_col = ei + E;
    const int nScanBlocks = (N + 255) / 256;

    // ---- fork: ss + CSR build on s2, layer-1 GEMM on default stream ----
    cudaEventRecord(evFork, 0);
    cudaStreamWaitEvent(s2, evFork, 0);

    ss_all_kernel<<<3, H3, 0, s2>>>(conv1_b, bn1_g, bn1_b, bn1_m, bn1_v,
                                    conv2_b, bn2_g, bn2_b, bn2_m, bn2_v,
                                    conv3_b, bn3_g, bn3_b, bn3_m, bn3_v, sc, sh);
    hist_kernel<<<(E + 255) / 256, 256, 0, s2>>>(e_col, cnt, E);
    partial_kernel<<<nScanBlocks, 256, 0, s2>>>(cnt, blockSum, N);
    scanwrite_kernel<<<nScanBlocks, 256, 0, s2>>>(cnt, blockSum, ptr, cursor, dis, N, nScanBlocks);
    scatter_kernel<<<(E + 255) / 256, 256, 0, s2>>>(e_row, e_col, dis, cursor, srcIdx, enorm, E);
    cudaEventRecord(evCsr, s2);

    const int gemmBlocks = (N + 127) / 128;
    const int h1Blocks = (N + 7) / 8;
    const int h2Blocks = (N + 15) / 16;

    // default stream: layer-1 projection GEMM starts immediately
    gemm_conv_fused<<<gemmBlocks, 512, FUSED_SMEM_BYTES>>>(x, conv1_W,
                                                           bn1_g, bn1_b, bn1_m, bn1_v, conv1_b,
                                                           Ha, (__half2*)Zr16, N, DD);

    // ---- join: SpMM needs CSR + ss ----
    cudaStreamWaitEvent(0, evCsr, 0);

    // ---- layer 1 aggregation ----
    spmm_h1<<<h1Blocks, 256>>>((const uint2*)Zr16, (float4*)Ha, (uint2*)Zs16,
                               ptr, srcIdx, enorm, dis, sc + 60, sh + 60, N);
    spmm_h2<<<h2Blocks, 256>>>((const uint2*)Zs16, (float4*)Ha,
                               ptr, srcIdx, enorm, dis, sc + 120, sh + 120, N);

    // ---- layer 2 (K=180) ----
    gemm_conv_fused<<<gemmBlocks, 512, FUSED_SMEM_BYTES>>>(Ha, conv2_W,
                                                           bn2_g, bn2_b, bn2_m, bn2_v, conv2_b,
                                                           Hb, (__half2*)Zr16, N, H3);
    spmm_h1<<<h1Blocks, 256>>>((const uint2*)Zr16, (float4*)Hb, (uint2*)Zs16,
                               ptr, srcIdx, enorm, dis, sc + H3 + 60, sh + H3 + 60, N);
    spmm_h2<<<h2Blocks, 256>>>((const uint2*)Zs16, (float4*)Hb,
                               ptr, srcIdx, enorm, dis, sc + H3 + 120, sh + H3 + 120, N);

    // ---- layer 3 (K=180) ----
    gemm_conv_fused<<<gemmBlocks, 512, FUSED_SMEM_BYTES>>>(Hb, conv3_W,
                                                           bn3_g, bn3_b, bn3_m, bn3_v, conv3_b,
                                                           Ha, (__half2*)Zr16, N, H3);
    spmm_h1<<<h1Blocks, 256>>>((const uint2*)Zr16, (float4*)Ha, (uint2*)Zs16,
                               ptr, srcIdx, enorm, dis, sc + 2 * H3 + 60, sh + 2 * H3 + 60, N);
    spmm_h2<<<h2Blocks, 256>>>((const uint2*)Zs16, (float4*)Ha,
                               ptr, srcIdx, enorm, dis, sc + 2 * H3 + 120, sh + 2 * H3 + 120, N);

    // ---- final linear ----
    gemm_final<<<gemmBlocks, 256, GEMM_SMEM_BYTES>>>(Ha, lin_W, lin_b, out, N, H3, CC);
}

// round 17
// speedup vs baseline: 1.0909x; 1.0298x over previous
#include <cuda_runtime.h>
#include <cuda_bf16.h>
#include <cuda_fp16.h>

// ---------------- problem constants ----------------
#define NN 50000
#define EE 400000
#define DD 128
#define HH 60
#define H3 180
#define CC 40
#define BN_EPS 1e-5f

// ---------------- static scratch ----------------
__device__ __half g_Zr16[NN * 120];   // raw p=1,2 projections (fp16)
__device__ __half g_Zs16[NN * 64];    // raw hop-1 result for p=2 (fp16)
__device__ float g_Ha[NN * H3];
__device__ float g_Hb[NN * H3];
__device__ float g_scale[3 * H3];
__device__ float g_shift[3 * H3];
__device__ int   g_cnt[NN];           // zero-init; re-zeroed by scanwrite each call
__device__ int   g_ptr[NN + 1];
__device__ int   g_cursor[NN];
__device__ int   g_blockSum[256];
__device__ int   g_srcIdx[EE];
__device__ float g_enorm[EE];
__device__ float g_dis[NN];

// ---------------- CSR build (scalar, 1 edge/thread) ----------------
__global__ void hist_kernel(const int* __restrict__ col, int* __restrict__ cnt, int E) {
    int e = blockIdx.x * blockDim.x + threadIdx.x;
    if (e < E) atomicAdd(&cnt[col[e]], 1);
}

__global__ void partial_kernel(const int* __restrict__ cnt, int* __restrict__ blockSum, int n) {
    __shared__ int ws[8];
    int i = blockIdx.x * 256 + threadIdx.x;
    int lane = threadIdx.x & 31, wid = threadIdx.x >> 5;
    int v = (i < n) ? cnt[i] : 0;
    #pragma unroll
    for (int off = 16; off > 0; off >>= 1) v += __shfl_down_sync(0xffffffffu, v, off);
    if (lane == 0) ws[wid] = v;
    __syncthreads();
    if (wid == 0) {
        int s = (lane < 8) ? ws[lane] : 0;
        #pragma unroll
        for (int off = 4; off > 0; off >>= 1) s += __shfl_down_sync(0xffffffffu, s, off);
        if (lane == 0) blockSum[blockIdx.x] = s;
    }
}

// fused: scan blockSum (redundantly per block), per-chunk scan, write ptr/cursor/dis,
// zero cnt for the next call/replay.
__global__ void scanwrite_kernel(int* __restrict__ cnt, const int* __restrict__ blockSum,
                                 int* __restrict__ ptr, int* __restrict__ cursor,
                                 float* __restrict__ dis, int n, int nBlocks) {
    __shared__ int ws[8];
    __shared__ int sOff[256];
    const int tid = threadIdx.x, lane = tid & 31, wid = tid >> 5;

    int bv = (tid < nBlocks) ? blockSum[tid] : 0;
    int bx = bv;
    #pragma unroll
    for (int off = 1; off < 32; off <<= 1) {
        int t = __shfl_up_sync(0xffffffffu, bx, off);
        if (lane >= off) bx += t;
    }
    if (lane == 31) ws[wid] = bx;
    __syncthreads();
    if (wid == 0 && lane < 8) {
        int w = ws[lane];
        #pragma unroll
        for (int off = 1; off < 8; off <<= 1) {
            int t = __shfl_up_sync(0xffu, w, off);
            if (lane >= off) w += t;
        }
        ws[lane] = w;
    }
    __syncthreads();
    {
        int bwoff = wid ? ws[wid - 1] : 0;
        sOff[tid] = bwoff + bx - bv;
    }
    __syncthreads();
    const int myOff = sOff[blockIdx.x];
    __syncthreads();

    int i = blockIdx.x * 256 + tid;
    int v = (i < n) ? cnt[i] : 0;
    int x = v;
    #pragma unroll
    for (int off = 1; off < 32; off <<= 1) {
        int t = __shfl_up_sync(0xffffffffu, x, off);
        if (lane >= off) x += t;
    }
    if (lane == 31) ws[wid] = x;
    __syncthreads();
    if (wid == 0 && lane < 8) {
        int w = ws[lane];
        #pragma unroll
        for (int off = 1; off < 8; off <<= 1) {
            int t = __shfl_up_sync(0xffu, w, off);
            if (lane >= off) w += t;
        }
        ws[lane] = w;
    }
    __syncthreads();
    int woff = wid ? ws[wid - 1] : 0;
    int excl = myOff + woff + x - v;
    if (i < n) {
        ptr[i] = excl;
        cursor[i] = excl;
        dis[i] = rsqrtf((float)(v + 1));   // +1 self loop
        if (i == n - 1) ptr[n] = excl + v;
        cnt[i] = 0;
    }
}

__global__ void scatter_kernel(const int* __restrict__ row, const int* __restrict__ col,
                               const float* __restrict__ dis, int* __restrict__ cursor,
                               int* __restrict__ srcIdx, float* __restrict__ enorm, int E) {
    int e = blockIdx.x * blockDim.x + threadIdx.x;
    if (e < E) {
        int r = row[e], c = col[e];
        int pos = atomicAdd(&cursor[c], 1);
        srcIdx[pos] = r;
        enorm[pos]  = dis[r] * dis[c];
    }
}

// ---------------- folded BN scale/shift precompute (for SpMM epilogues) ----
__global__ void ss_all_kernel(const float* __restrict__ b1c, const float* __restrict__ g1,
                              const float* __restrict__ b1, const float* __restrict__ m1,
                              const float* __restrict__ v1,
                              const float* __restrict__ b2c, const float* __restrict__ g2,
                              const float* __restrict__ b2, const float* __restrict__ m2,
                              const float* __restrict__ v2,
                              const float* __restrict__ b3c, const float* __restrict__ g3,
                              const float* __restrict__ b3, const float* __restrict__ m3,
                              const float* __restrict__ v3,
                              float* __restrict__ sc, float* __restrict__ sh) {
    int L = blockIdx.x;
    int c = threadIdx.x;
    if (c >= H3) return;
    const float* cb = (L == 0) ? b1c : (L == 1) ? b2c : b3c;
    const float* g  = (L == 0) ? g1  : (L == 1) ? g2  : g3;
    const float* b  = (L == 0) ? b1  : (L == 1) ? b2  : b3;
    const float* m  = (L == 0) ? m1  : (L == 1) ? m2  : m3;
    const float* v  = (L == 0) ? v1  : (L == 1) ? v2  : v3;
    float s = g[c] * rsqrtf(v[c] + BN_EPS);
    sc[L * H3 + c] = s;
    sh[L * H3 + c] = (cb[c] - m[c]) * s + b[c];
}

// ---------------- fp16 gather helpers ----------------
__device__ __forceinline__ float4 h4_to_f4(uint2 raw) {
    __half2 p0 = *reinterpret_cast<__half2*>(&raw.x);
    __half2 p1 = *reinterpret_cast<__half2*>(&raw.y);
    float2 f0 = __half22float2(p0);
    float2 f1 = __half22float2(p1);
    return make_float4(f0.x, f0.y, f1.x, f1.y);
}

__device__ __forceinline__ uint2 f4_to_h4(float4 v) {
    __half2 p0 = __floats2half2_rn(v.x, v.y);
    __half2 p1 = __floats2half2_rn(v.z, v.w);
    uint2 r;
    r.x = *reinterpret_cast<unsigned*>(&p0);
    r.y = *reinterpret_cast<unsigned*>(&p1);
    return r;
}

// ---------------- SpMM hop 1: 120-wide fp16 gather (clean 4-edge unroll) ----
__global__ void __launch_bounds__(256)
spmm_h1(const uint2* __restrict__ Zr2, float4* __restrict__ H, uint2* __restrict__ Zs2,
        const int* __restrict__ ptr, const int* __restrict__ srcIdx,
        const float* __restrict__ enorm, const float* __restrict__ dis,
        const float* __restrict__ ssS, const float* __restrict__ ssH, int N) {
    const int lane = threadIdx.x & 31;
    const int node = blockIdx.x * 8 + (threadIdx.x >> 5);
    if (node >= N) return;
    const bool act = lane < 30;

    float d = dis[node];
    float dd = d * d;
    float4 acc = make_float4(0.f, 0.f, 0.f, 0.f);
    if (act) {
        float4 v = h4_to_f4(Zr2[node * 30 + lane]);
        acc.x = dd * v.x; acc.y = dd * v.y; acc.z = dd * v.z; acc.w = dd * v.w;
    }

    int s = ptr[node], e = ptr[node + 1];
    int k = s;
    for (; k + 3 < e; k += 4) {
        int s0 = srcIdx[k], s1 = srcIdx[k + 1], s2 = srcIdx[k + 2], s3 = srcIdx[k + 3];
        float w0 = enorm[k], w1 = enorm[k + 1], w2 = enorm[k + 2], w3 = enorm[k + 3];
        if (act) {
            float4 v0 = h4_to_f4(Zr2[s0 * 30 + lane]);
            float4 v1 = h4_to_f4(Zr2[s1 * 30 + lane]);
            float4 v2 = h4_to_f4(Zr2[s2 * 30 + lane]);
            float4 v3 = h4_to_f4(Zr2[s3 * 30 + lane]);
            acc.x += w0 * v0.x; acc.y += w0 * v0.y; acc.z += w0 * v0.z; acc.w += w0 * v0.w;
            acc.x += w1 * v1.x; acc.y += w1 * v1.y; acc.z += w1 * v1.z; acc.w += w1 * v1.w;
            acc.x += w2 * v2.x; acc.y += w2 * v2.y; acc.z += w2 * v2.z; acc.w += w2 * v2.w;
            acc.x += w3 * v3.x; acc.y += w3 * v3.y; acc.z += w3 * v3.z; acc.w += w3 * v3.w;
        }
    }
    for (; k < e; k++) {
        int s0 = srcIdx[k];
        float w0 = enorm[k];
        if (act) {
            float4 v0 = h4_to_f4(Zr2[s0 * 30 + lane]);
            acc.x += w0 * v0.x; acc.y += w0 * v0.y; acc.z += w0 * v0.z; acc.w += w0 * v0.w;
        }
    }

    if (lane < 15) {
        float4 sc = reinterpret_cast<const float4*>(ssS)[lane];
        float4 sh = reinterpret_cast<const float4*>(ssH)[lane];
        float4 o;
        o.x = acc.x * sc.x + sh.x;
        o.y = acc.y * sc.y + sh.y;
        o.z = acc.z * sc.z + sh.z;
        o.w = acc.w * sc.w + sh.w;
        H[node * 45 + 15 + lane] = o;                // H[:, 60:120] fp32
    } else if (act) {
        Zs2[node * 15 + (lane - 15)] = f4_to_h4(acc); // raw p=2 hop-1 fp16
    }
}

// ---------------- SpMM hop 2: 60-wide fp16 gather (clean 4-edge unroll) ----
__global__ void __launch_bounds__(256)
spmm_h2(const uint2* __restrict__ Zs2, float4* __restrict__ H,
        const int* __restrict__ ptr, const int* __restrict__ srcIdx,
        const float* __restrict__ enorm, const float* __restrict__ dis,
        const float* __restrict__ ssS, const float* __restrict__ ssH, int N) {
    const int l = threadIdx.x & 15;
    const int node = blockIdx.x * 16 + (threadIdx.x >> 4);
    if (node >= N) return;
    const bool act = l < 15;

    float d = dis[node];
    float dd = d * d;
    float4 acc = make_float4(0.f, 0.f, 0.f, 0.f);
    if (act) {
        float4 v = h4_to_f4(Zs2[node * 15 + l]);
        acc.x = dd * v.x; acc.y = dd * v.y; acc.z = dd * v.z; acc.w = dd * v.w;
    }

    int s = ptr[node], e = ptr[node + 1];
    int k = s;
    for (; k + 3 < e; k += 4) {
        int s0 = srcIdx[k], s1 = srcIdx[k + 1], s2 = srcIdx[k + 2], s3 = srcIdx[k + 3];
        float w0 = enorm[k], w1 = enorm[k + 1], w2 = enorm[k + 2], w3 = enorm[k + 3];
        if (act) {
            float4 v0 = h4_to_f4(Zs2[s0 * 15 + l]);
            float4 v1 = h4_to_f4(Zs2[s1 * 15 + l]);
            float4 v2 = h4_to_f4(Zs2[s2 * 15 + l]);
            float4 v3 = h4_to_f4(Zs2[s3 * 15 + l]);
            acc.x += w0 * v0.x; acc.y += w0 * v0.y; acc.z += w0 * v0.z; acc.w += w0 * v0.w;
            acc.x += w1 * v1.x; acc.y += w1 * v1.y; acc.z += w1 * v1.z; acc.w += w1 * v1.w;
            acc.x += w2 * v2.x; acc.y += w2 * v2.y; acc.z += w2 * v2.z; acc.w += w2 * v2.w;
            acc.x += w3 * v3.x; acc.y += w3 * v3.y; acc.z += w3 * v3.z; acc.w += w3 * v3.w;
        }
    }
    for (; k < e; k++) {
        int s0 = srcIdx[k];
        float w0 = enorm[k];
        if (act) {
            float4 v0 = h4_to_f4(Zs2[s0 * 15 + l]);
            acc.x += w0 * v0.x; acc.y += w0 * v0.y; acc.z += w0 * v0.z; acc.w += w0 * v0.w;
        }
    }

    if (act) {
        float4 sc = reinterpret_cast<const float4*>(ssS)[l];
        float4 sh = reinterpret_cast<const float4*>(ssH)[l];
        float4 o;
        o.x = acc.x * sc.x + sh.x;
        o.y = acc.y * sc.y + sh.y;
        o.z = acc.z * sc.z + sh.z;
        o.w = acc.w * sc.w + sh.w;
        H[node * 45 + 30 + l] = o;          // H[:, 120:180] fp32
    }
}

// ---------------- bf16 split helpers ----------------
__device__ __forceinline__ unsigned pk_bf2(float x, float y) {
    __nv_bfloat162 p = __floats2bfloat162_rn(x, y);
    return *reinterpret_cast<unsigned*>(&p);
}

__device__ __forceinline__ void mma_bf16(float* d, unsigned a0, unsigned a1,
                                         unsigned a2, unsigned a3,
                                         unsigned b0, unsigned b1) {
    asm volatile("mma.sync.aligned.m16n8k16.row.col.f32.bf16.bf16.f32 "
                 "{%0,%1,%2,%3}, {%4,%5,%6,%7}, {%8,%9}, {%0,%1,%2,%3};"
                 : "+f"(d[0]), "+f"(d[1]), "+f"(d[2]), "+f"(d[3])
                 : "r"(a0), "r"(a1), "r"(a2), "r"(a3), "r"(b0), "r"(b1));
}

template <int ITERS, int THREADS>
__device__ __forceinline__ void ldg_tile(const float* __restrict__ base, int row0,
                                         int rows_max, int K, int kb, int tid,
                                         float2 v[ITERS]) {
    #pragma unroll
    for (int it = 0; it < ITERS; it++) {
        int idx = tid + it * THREADS;
        int r = idx >> 4, j = idx & 15;
        int gr = row0 + r, gk = kb + 2 * j;
        v[it] = (gr < rows_max && gk < K)
                ? *reinterpret_cast<const float2*>(&base[(size_t)gr * K + gk])
                : make_float2(0.f, 0.f);
    }
}

template <int ITERS, int THREADS>
__device__ __forceinline__ void sts_tile(unsigned* buf, int tid, const float2 v[ITERS]) {
    #pragma unroll
    for (int it = 0; it < ITERS; it++) {
        int idx = tid + it * THREADS;
        int r = idx >> 4, j = idx & 15;
        float2 a = v[it];
        __nv_bfloat16 hx = __float2bfloat16_rn(a.x);
        __nv_bfloat16 hy = __float2bfloat16_rn(a.y);
        float mx = a.x - __bfloat162float(hx);
        float my = a.y - __bfloat162float(hy);
        __nv_bfloat162 hp; hp.x = hx; hp.y = hy;
        unsigned hi = *reinterpret_cast<unsigned*>(&hp);
        unsigned mid = pk_bf2(mx, my);
        *reinterpret_cast<uint2*>(&buf[r * 36 + 2 * j]) = make_uint2(hi, mid);
    }
}

// ---------------- critical-path GEMM: A[N x K] @ Wz[120 x K]^T -> Zr fp16 ----
// 128x128 tile, 512 threads, 4M x 4N warps, warp tile 32x32.
#define GZR_SMEM_BYTES ((2 * 128 * 36 + 2 * 128 * 36) * 4)

__global__ void __launch_bounds__(512, 1)
gemm_Zr(const float* __restrict__ A, const float* __restrict__ Wz,
        __half2* __restrict__ Zr, int N, int K) {
    extern __shared__ unsigned smem_u[];
    unsigned* sA = smem_u;                    // [2][128][36]
    unsigned* sW = smem_u + 2 * 128 * 36;     // [2][128][36]

    const int tid  = threadIdx.x;
    const int lane = tid & 31;
    const int wid  = tid >> 5;
    const int warpM = wid & 3;    // 4 x 32 rows
    const int warpN = wid >> 2;   // 4 x 32 cols
    const int row0 = blockIdx.x * 128;
    const int g = lane >> 2;
    const int t = lane & 3;
    const int mBase = warpM * 32;

    float acc[2][4][4];
    #pragma unroll
    for (int mt = 0; mt < 2; mt++)
        #pragma unroll
        for (int nt = 0; nt < 4; nt++)
            #pragma unroll
            for (int j = 0; j < 4; j++) acc[mt][nt][j] = 0.0f;

    float2 aReg[4], wReg[4];
    ldg_tile<4, 512>(A, row0, N, K, 0, tid, aReg);
    ldg_tile<4, 512>(Wz, 0, 120, K, 0, tid, wReg);
    sts_tile<4, 512>(sA, tid, aReg);
    sts_tile<4, 512>(sW, tid, wReg);
    __syncthreads();

    const int nC = (K + 31) / 32;
    for (int c = 0; c < nC; c++) {
        const int cur = c & 1;
        const unsigned* cA = sA + cur * 128 * 36;
        const unsigned* cW = sW + cur * 128 * 36;
        if (c + 1 < nC) {
            ldg_tile<4, 512>(A, row0, N, K, (c + 1) * 32, tid, aReg);
            ldg_tile<4, 512>(Wz, 0, 120, K, (c + 1) * 32, tid, wReg);
        }
        #pragma unroll
        for (int ks = 0; ks < 2; ks++) {
            const int pb = 2 * (8 * ks + t);
            uint2 aF[2][4];
            #pragma unroll
            for (int mt = 0; mt < 2; mt++) {
                const int br = mBase + mt * 16 + g;
                aF[mt][0] = *reinterpret_cast<const uint2*>(&cA[br * 36 + pb]);
                aF[mt][1] = *reinterpret_cast<const uint2*>(&cA[(br + 8) * 36 + pb]);
                aF[mt][2] = *reinterpret_cast<const uint2*>(&cA[br * 36 + pb + 8]);
                aF[mt][3] = *reinterpret_cast<const uint2*>(&cA[(br + 8) * 36 + pb + 8]);
            }
            #pragma unroll
            for (int nt = 0; nt < 4; nt++) {
                const int bn_ = warpN * 32 + nt * 8 + g;
                uint2 b0 = *reinterpret_cast<const uint2*>(&cW[bn_ * 36 + pb]);
                uint2 b1 = *reinterpret_cast<const uint2*>(&cW[bn_ * 36 + pb + 8]);
                #pragma unroll
                for (int mt = 0; mt < 2; mt++) {
                    mma_bf16(acc[mt][nt], aF[mt][0].x, aF[mt][1].x, aF[mt][2].x, aF[mt][3].x, b0.x, b1.x); // hi*hi
                    mma_bf16(acc[mt][nt], aF[mt][0].x, aF[mt][1].x, aF[mt][2].x, aF[mt][3].x, b0.y, b1.y); // hi*mid
                    mma_bf16(acc[mt][nt], aF[mt][0].y, aF[mt][1].y, aF[mt][2].y, aF[mt][3].y, b0.x, b1.x); // mid*hi
                }
            }
        }
        if (c + 1 < nC) {
            sts_tile<4, 512>(sA + ((c + 1) & 1) * 128 * 36, tid, aReg);
            sts_tile<4, 512>(sW + ((c + 1) & 1) * 128 * 36, tid, wReg);
        }
        __syncthreads();
    }

    #pragma unroll
    for (int mt = 0; mt < 2; mt++) {
        const int rlo = row0 + mBase + mt * 16 + g;
        #pragma unroll
        for (int nt = 0; nt < 4; nt++) {
            const int c0 = warpN * 32 + nt * 8 + 2 * t;   // even; pair (c0, c0+1)
            if (c0 >= 120) continue;
            int zc = c0 >> 1;   // half2 index, 60 per row
            __half2 h0 = __floats2half2_rn(acc[mt][nt][0], acc[mt][nt][1]);
            __half2 h1 = __floats2half2_rn(acc[mt][nt][2], acc[mt][nt][3]);
            if (rlo < N)     Zr[(size_t)rlo * 60 + zc] = h0;
            if (rlo + 8 < N) Zr[(size_t)(rlo + 8) * 60 + zc] = h1;
        }
    }
}

// ---------------- side-stream GEMM: A[N x K] @ W60[60 x K]^T -> H[:,0:60] (BN) ----
// 128x64 tile, 256 threads, 2 blocks/SM. BN fold computed in prologue.
#define GH0_SMEM_BYTES ((2 * 128 * 36 + 2 * 64 * 36) * 4)

__global__ void __launch_bounds__(256, 2)
gemm_H0(const float* __restrict__ A, const float* __restrict__ W60,
        const float* __restrict__ bng, const float* __restrict__ bnb,
        const float* __restrict__ bnm, const float* __restrict__ bnv,
        const float* __restrict__ convb,
        float* __restrict__ Hdst, int N, int K) {
    extern __shared__ unsigned smem_u[];
    unsigned* sA = smem_u;                    // [2][128][36]
    unsigned* sW = smem_u + 2 * 128 * 36;     // [2][64][36]
    __shared__ float sSc[60], sSh[60];

    const int tid  = threadIdx.x;
    const int lane = tid & 31;
    const int wid  = tid >> 5;
    const int warpM = wid & 3;
    const int warpN = wid >> 2;
    const int row0 = blockIdx.x * 128;
    const int g = lane >> 2;
    const int t = lane & 3;
    const int mBase = warpM * 32;

    if (tid < 60) {
        float s = bng[tid] * rsqrtf(bnv[tid] + BN_EPS);
        sSc[tid] = s;
        sSh[tid] = (convb[tid] - bnm[tid]) * s + bnb[tid];
    }

    float acc[2][4][4];
    #pragma unroll
    for (int mt = 0; mt < 2; mt++)
        #pragma unroll
        for (int nt = 0; nt < 4; nt++)
            #pragma unroll
            for (int j = 0; j < 4; j++) acc[mt][nt][j] = 0.0f;

    float2 aReg[8], wReg[4];
    ldg_tile<8, 256>(A, row0, N, K, 0, tid, aReg);
    ldg_tile<4, 256>(W60, 0, 60, K, 0, tid, wReg);
    sts_tile<8, 256>(sA, tid, aReg);
    sts_tile<4, 256>(sW, tid, wReg);
    __syncthreads();

    const int nC = (K + 31) / 32;
    for (int c = 0; c < nC; c++) {
        const int cur = c & 1;
        const unsigned* cA = sA + cur * 128 * 36;
        const unsigned* cW = sW + cur * 64 * 36;
        if (c + 1 < nC) {
            ldg_tile<8, 256>(A, row0, N, K, (c + 1) * 32, tid, aReg);
            ldg_tile<4, 256>(W60, 0, 60, K, (c + 1) * 32, tid, wReg);
        }
        #pragma unroll
        for (int ks = 0; ks < 2; ks++) {
            const int pb = 2 * (8 * ks + t);
            uint2 aF[2][4];
            #pragma unroll
            for (int mt = 0; mt < 2; mt++) {
                const int br = mBase + mt * 16 + g;
                aF[mt][0] = *reinterpret_cast<const uint2*>(&cA[br * 36 + pb]);
                aF[mt][1] = *reinterpret_cast<const uint2*>(&cA[(br + 8) * 36 + pb]);
                aF[mt][2] = *reinterpret_cast<const uint2*>(&cA[br * 36 + pb + 8]);
                aF[mt][3] = *reinterpret_cast<const uint2*>(&cA[(br + 8) * 36 + pb + 8]);
            }
            #pragma unroll
            for (int nt = 0; nt < 4; nt++) {
                const int bn_ = warpN * 32 + nt * 8 + g;
                uint2 b0 = *reinterpret_cast<const uint2*>(&cW[bn_ * 36 + pb]);
                uint2 b1 = *reinterpret_cast<const uint2*>(&cW[bn_ * 36 + pb + 8]);
                #pragma unroll
                for (int mt = 0; mt < 2; mt++) {
                    mma_bf16(acc[mt][nt], aF[mt][0].x, aF[mt][1].x, aF[mt][2].x, aF[mt][3].x, b0.x, b1.x);
                    mma_bf16(acc[mt][nt], aF[mt][0].x, aF[mt][1].x, aF[mt][2].x, aF[mt][3].x, b0.y, b1.y);
                    mma_bf16(acc[mt][nt], aF[mt][0].y, aF[mt][1].y, aF[mt][2].y, aF[mt][3].y, b0.x, b1.x);
                }
            }
        }
        if (c + 1 < nC) {
            sts_tile<8, 256>(sA + ((c + 1) & 1) * 128 * 36, tid, aReg);
            sts_tile<4, 256>(sW + ((c + 1) & 1) * 64 * 36, tid, wReg);
        }
        __syncthreads();
    }

    #pragma unroll
    for (int mt = 0; mt < 2; mt++) {
        const int rlo = row0 + mBase + mt * 16 + g;
        #pragma unroll
        for (int nt = 0; nt < 4; nt++) {
            const int cb = warpN * 32 + nt * 8 + 2 * t;
            #pragma unroll
            for (int jj = 0; jj < 2; jj++) {
                int c = cb + jj;
                if (c >= 60) continue;
                float sc = sSc[c], sh = sSh[c];
                if (rlo < N)     Hdst[(size_t)rlo * H3 + c] = acc[mt][nt][jj] * sc + sh;
                if (rlo + 8 < N) Hdst[(size_t)(rlo + 8) * H3 + c] = acc[mt][nt][2 + jj] * sc + sh;
            }
        }
    }
}

// ---------------- final linear GEMM (128x64 tile, bias only) ----------------
#define GEMM_SMEM_BYTES ((2 * 128 * 36 + 2 * 64 * 36) * 4)

__global__ void __launch_bounds__(256, 2)
gemm_final(const float* __restrict__ A, const float* __restrict__ W,
           const float* __restrict__ bias, float* __restrict__ outF, int N, int K, int Cc) {
    extern __shared__ unsigned smem_u[];
    unsigned* sA = smem_u;                    // [2][128][36]
    unsigned* sW = smem_u + 2 * 128 * 36;     // [2][64][36]

    const int tid  = threadIdx.x;
    const int lane = tid & 31;
    const int wid  = tid >> 5;
    const int warpM = wid & 3;
    const int warpN = wid >> 2;
    const int row0 = blockIdx.x * 128;
    const int g = lane >> 2;
    const int t = lane & 3;
    const int mBase = warpM * 32;

    float acc[2][4][4];
    #pragma unroll
    for (int mt = 0; mt < 2; mt++)
        #pragma unroll
        for (int nt = 0; nt < 4; nt++)
            #pragma unroll
            for (int j = 0; j < 4; j++) acc[mt][nt][j] = 0.0f;

    float2 aReg[8], wReg[4];
    ldg_tile<8, 256>(A, row0, N, K, 0, tid, aReg);
    ldg_tile<4, 256>(W, 0, Cc, K, 0, tid, wReg);
    sts_tile<8, 256>(sA, tid, aReg);
    sts_tile<4, 256>(sW, tid, wReg);
    __syncthreads();

    const int nC = (K + 31) / 32;
    for (int c = 0; c < nC; c++) {
        const int cur = c & 1;
        const unsigned* cA = sA + cur * 128 * 36;
        const unsigned* cW = sW + cur * 64 * 36;
        if (c + 1 < nC) {
            ldg_tile<8, 256>(A, row0, N, K, (c + 1) * 32, tid, aReg);
            ldg_tile<4, 256>(W, 0, Cc, K, (c + 1) * 32, tid, wReg);
        }
        #pragma unroll
        for (int ks = 0; ks < 2; ks++) {
            const int pb = 2 * (8 * ks + t);
            uint2 aF[2][4];
            #pragma unroll
            for (int mt = 0; mt < 2; mt++) {
                const int br = mBase + mt * 16 + g;
                aF[mt][0] = *reinterpret_cast<const uint2*>(&cA[br * 36 + pb]);
                aF[mt][1] = *reinterpret_cast<const uint2*>(&cA[(br + 8) * 36 + pb]);
                aF[mt][2] = *reinterpret_cast<const uint2*>(&cA[br * 36 + pb + 8]);
                aF[mt][3] = *reinterpret_cast<const uint2*>(&cA[(br + 8) * 36 + pb + 8]);
            }
            #pragma unroll
            for (int nt = 0; nt < 4; nt++) {
                const int bn_ = warpN * 32 + nt * 8 + g;
                uint2 b0 = *reinterpret_cast<const uint2*>(&cW[bn_ * 36 + pb]);
                uint2 b1 = *reinterpret_cast<const uint2*>(&cW[bn_ * 36 + pb + 8]);
                #pragma unroll
                for (int mt = 0; mt < 2; mt++) {
                    mma_bf16(acc[mt][nt], aF[mt][0].x, aF[mt][1].x, aF[mt][2].x, aF[mt][3].x, b0.x, b1.x);
                    mma_bf16(acc[mt][nt], aF[mt][0].x, aF[mt][1].x, aF[mt][2].x, aF[mt][3].x, b0.y, b1.y);
                    mma_bf16(acc[mt][nt], aF[mt][0].y, aF[mt][1].y, aF[mt][2].y, aF[mt][3].y, b0.x, b1.x);
                }
            }
        }
        if (c + 1 < nC) {
            sts_tile<8, 256>(sA + ((c + 1) & 1) * 128 * 36, tid, aReg);
            sts_tile<4, 256>(sW + ((c + 1) & 1) * 64 * 36, tid, wReg);
        }
        __syncthreads();
    }

    #pragma unroll
    for (int mt = 0; mt < 2; mt++) {
        const int rlo = row0 + mBase + mt * 16 + g;
        #pragma unroll
        for (int nt = 0; nt < 4; nt++) {
            const int cb = warpN * 32 + nt * 8 + 2 * t;
            #pragma unroll
            for (int jj = 0; jj < 2; jj++) {
                int c = cb + jj;
                if (c >= Cc) continue;
                float add = bias[c];
                if (rlo < N)     outF[(size_t)rlo * CC + c] = acc[mt][nt][jj] + add;
                if (rlo + 8 < N) outF[(size_t)(rlo + 8) * CC + c] = acc[mt][nt][2 + jj] + add;
            }
        }
    }
}

// ---------------- host launch ----------------
extern "C" void kernel_launch(void* const* d_in, const int* in_sizes, int n_in,
                              void* d_out, int out_size) {
    const float* x       = (const float*)d_in[0];
    const int*   ei      = (const int*)d_in[1];
    const float* conv1_W = (const float*)d_in[2];
    const float* conv1_b = (const float*)d_in[3];
    const float* conv2_W = (const float*)d_in[4];
    const float* conv2_b = (const float*)d_in[5];
    const float* conv3_W = (const float*)d_in[6];
    const float* conv3_b = (const float*)d_in[7];
    const float* bn1_g = (const float*)d_in[8];
    const float* bn1_b = (const float*)d_in[9];
    const float* bn1_m = (const float*)d_in[10];
    const float* bn1_v = (const float*)d_in[11];
    const float* bn2_g = (const float*)d_in[12];
    const float* bn2_b = (const float*)d_in[13];
    const float* bn2_m = (const float*)d_in[14];
    const float* bn2_v = (const float*)d_in[15];
    const float* bn3_g = (const float*)d_in[16];
    const float* bn3_b = (const float*)d_in[17];
    const float* bn3_m = (const float*)d_in[18];
    const float* bn3_v = (const float*)d_in[19];
    const float* lin_W = (const float*)d_in[20];
    const float* lin_b = (const float*)d_in[21];
    float* out = (float*)d_out;

    const int N = in_sizes[0] / DD;
    const int E = in_sizes[1] / 2;

    float *Ha, *Hb, *enorm, *dis, *sc, *sh;
    __half *Zr16, *Zs16;
    int *cnt, *ptr, *cursor, *srcIdx, *blockSum;
    cudaGetSymbolAddress((void**)&Zr16, g_Zr16);
    cudaGetSymbolAddress((void**)&Zs16, g_Zs16);
    cudaGetSymbolAddress((void**)&Ha, g_Ha);
    cudaGetSymbolAddress((void**)&Hb, g_Hb);
    cudaGetSymbolAddress((void**)&sc, g_scale);
    cudaGetSymbolAddress((void**)&sh, g_shift);
    cudaGetSymbolAddress((void**)&cnt, g_cnt);
    cudaGetSymbolAddress((void**)&ptr, g_ptr);
    cudaGetSymbolAddress((void**)&cursor, g_cursor);
    cudaGetSymbolAddress((void**)&srcIdx, g_srcIdx);
    cudaGetSymbolAddress((void**)&enorm, g_enorm);
    cudaGetSymbolAddress((void**)&dis, g_dis);
    cudaGetSymbolAddress((void**)&blockSum, g_blockSum);

    cudaFuncSetAttribute(gemm_Zr,
                         cudaFuncAttributeMaxDynamicSharedMemorySize, GZR_SMEM_BYTES);
    cudaFuncSetAttribute(gemm_H0,
                         cudaFuncAttributeMaxDynamicSharedMemorySize, GH0_SMEM_BYTES);
    cudaFuncSetAttribute(gemm_final,
                         cudaFuncAttributeMaxDynamicSharedMemorySize, GEMM_SMEM_BYTES);

    // side stream + events (created once, pre-capture)
    static cudaStream_t s2 = nullptr;
    static cudaEvent_t evFork = nullptr, evCsr = nullptr;
    static cudaEvent_t evH0_1 = nullptr, evH0_2 = nullptr, evH0_3 = nullptr;
    static cudaEvent_t evH2_1 = nullptr, evH2_2 = nullptr;
    if (s2 == nullptr) {
        cudaStreamCreateWithFlags(&s2, cudaStreamNonBlocking);
        cudaEventCreateWithFlags(&evFork, cudaEventDisableTiming);
        cudaEventCreateWithFlags(&evCsr, cudaEventDisableTiming);
        cudaEventCreateWithFlags(&evH0_1, cudaEventDisableTiming);
        cudaEventCreateWithFlags(&evH0_2, cudaEventDisableTiming);
        cudaEventCreateWithFlags(&evH0_3, cudaEventDisableTiming);
        cudaEventCreateWithFlags(&evH2_1, cudaEventDisableTiming);
        cudaEventCreateWithFlags(&evH2_2, cudaEventDisableTiming);
    }

    const int* e_row = ei;
    const int* e_col = ei + E;
    const int nScanBlocks = (N + 255) / 256;
    const int gemmBlocks = (N + 127) / 128;
    const int h1Blocks = (N + 7) / 8;
    const int h2Blocks = (N + 15) / 16;

    // ---- fork ----
    cudaEventRecord(evFork, 0);
    cudaStreamWaitEvent(s2, evFork, 0);

    // s2: ss + CSR build, then layer-1 H0 GEMM
    ss_all_kernel<<<3, H3, 0, s2>>>(conv1_b, bn1_g, bn1_b, bn1_m, bn1_v,
                                    conv2_b, bn2_g, bn2_b, bn2_m, bn2_v,
                                    conv3_b, bn3_g, bn3_b, bn3_m, bn3_v, sc, sh);
    hist_kernel<<<(E + 255) / 256, 256, 0, s2>>>(e_col, cnt, E);
    partial_kernel<<<nScanBlocks, 256, 0, s2>>>(cnt, blockSum, N);
    scanwrite_kernel<<<nScanBlocks, 256, 0, s2>>>(cnt, blockSum, ptr, cursor, dis, N, nScanBlocks);
    scatter_kernel<<<(E + 255) / 256, 256, 0, s2>>>(e_row, e_col, dis, cursor, srcIdx, enorm, E);
    cudaEventRecord(evCsr, s2);
    gemm_H0<<<gemmBlocks, 256, GH0_SMEM_BYTES, s2>>>(x, conv1_W,
                                                     bn1_g, bn1_b, bn1_m, bn1_v, conv1_b,
                                                     Ha, N, DD);
    cudaEventRecord(evH0_1, s2);

    // main: layer-1 Zr GEMM immediately
    gemm_Zr<<<gemmBlocks, 512, GZR_SMEM_BYTES>>>(x, conv1_W + 60 * DD, (__half2*)Zr16, N, DD);
    cudaStreamWaitEvent(0, evCsr, 0);
    spmm_h1<<<h1Blocks, 256>>>((const uint2*)Zr16, (float4*)Ha, (uint2*)Zs16,
                               ptr, srcIdx, enorm, dis, sc + 60, sh + 60, N);
    spmm_h2<<<h2Blocks, 256>>>((const uint2*)Zs16, (float4*)Ha,
                               ptr, srcIdx, enorm, dis, sc + 120, sh + 120, N);
    cudaEventRecord(evH2_1, 0);

    // s2: layer-2 H0 GEMM (needs full H1 = h2(1) + own gemm_H0(1))
    cudaStreamWaitEvent(s2, evH2_1, 0);
    gemm_H0<<<gemmBlocks, 256, GH0_SMEM_BYTES, s2>>>(Ha, conv2_W,
                                                     bn2_g, bn2_b, bn2_m, bn2_v, conv2_b,
                                                     Hb, N, H3);
    cudaEventRecord(evH0_2, s2);

    // main: layer-2 (Zr GEMM needs full H1 incl. H0 part)
    cudaStreamWaitEvent(0, evH0_1, 0);
    gemm_Zr<<<gemmBlocks, 512, GZR_SMEM_BYTES>>>(Ha, conv2_W + 60 * H3, (__half2*)Zr16, N, H3);
    spmm_h1<<<h1Blocks, 256>>>((const uint2*)Zr16, (float4*)Hb, (uint2*)Zs16,
                               ptr, srcIdx, enorm, dis, sc + H3 + 60, sh + H3 + 60, N);
    spmm_h2<<<h2Blocks, 256>>>((const uint2*)Zs16, (float4*)Hb,
                               ptr, srcIdx, enorm, dis, sc + H3 + 120, sh + H3 + 120, N);
    cudaEventRecord(evH2_2, 0);

    // s2: layer-3 H0 GEMM
    cudaStreamWaitEvent(s2, evH2_2, 0);
    gemm_H0<<<gemmBlocks, 256, GH0_SMEM_BYTES, s2>>>(Hb, conv3_W,
                                                     bn3_g, bn3_b, bn3_m, bn3_v, conv3_b,
                                                     Ha, N, H3);
    cudaEventRecord(evH0_3, s2);

    // main: layer-3
    cudaStreamWaitEvent(0, evH0_2, 0);
    gemm_Zr<<<gemmBlocks, 512, GZR_SMEM_BYTES>>>(Hb, conv3_W + 60 * H3, (__half2*)Zr16, N, H3);
    spmm_h1<<<h1Blocks, 256>>>((const uint2*)Zr16, (float4*)Ha, (uint2*)Zs16,
                               ptr, srcIdx, enorm, dis, sc + 2 * H3 + 60, sh + 2 * H3 + 60, N);
    spmm_h2<<<h2Blocks, 256>>>((const uint2*)Zs16, (float4*)Ha,
                               ptr, srcIdx, enorm, dis, sc + 2 * H3 + 120, sh + 2 * H3 + 120, N);

    // ---- final linear (needs full H3 incl. gemm_H0(3)) ----
    cudaStreamWaitEvent(0, evH0_3, 0);
    gemm_final<<<gemmBlocks, 256, GEMM_SMEM_BYTES>>>(Ha, lin_W, lin_b, out, N, H3, CC);
}